// round 2
// baseline (speedup 1.0000x reference)
#include <cuda_runtime.h>

#define TB 32
#define TT 50
#define TS 49
#define DD 100
#define NBR 6
#define SPQ 4
#define RK 10

// ---------------- device scratch (no allocations) ----------------
__device__ float g_eagg[2][TB][TS][DD];
__device__ float g_et[TB][TS][DD];
__device__ float g_gates[TB][TS][4 * DD];
__device__ float g_qsc[TB][TS][5][DD];
__device__ float g_ql[TB][TS][5];
__device__ int   g_idx[TB][TS][RK];
__device__ int   g_sval[TB][TS][RK];
__device__ float g_vq[DD], g_vk[DD];
__device__ float g_cq, g_ck;
__device__ float g_resp[2][DD];

// ---------------- A: collapse projections ----------------
__global__ void precompute_kernel(const float* __restrict__ W_query,
                                  const float* __restrict__ b_query,
                                  const float* __restrict__ W_key,
                                  const float* __restrict__ b_key,
                                  const float* __restrict__ W_w,
                                  const float* __restrict__ emb_r,
                                  const float* __restrict__ W_fusion,
                                  const float* __restrict__ b_fusion) {
    int tid = threadIdx.x;
    for (int k = tid; k < DD; k += 128) {
        float aq = 0.f, ak = 0.f;
        for (int d = 0; d < DD; d++) {
            aq += W_query[d * DD + k] * W_w[d];
            ak += W_key[d * DD + k] * W_w[DD + d];
        }
        g_vq[k] = aq; g_vk[k] = ak;
    }
    if (tid == 0) {
        float cq = 0.f, ck = 0.f;
        for (int d = 0; d < DD; d++) {
            cq += b_query[d] * W_w[d];
            ck += b_key[d] * W_w[DD + d];
        }
        g_cq = cq; g_ck = ck;
    }
    for (int i = tid; i < 2 * DD; i += 128) {
        int r = i / DD, d = i % DD;
        float a = b_fusion[d];
        for (int k = 0; k < DD; k++)
            a += emb_r[r * DD + k] * W_fusion[d * 2 * DD + DD + k];
        g_resp[r][d] = a;
    }
}

// ---------------- B: graph aggregation, one CTA per (t,b,side) ----------------
__global__ __launch_bounds__(256) void agg_kernel(
    const int* __restrict__ user, const int* __restrict__ question,
    const int* __restrict__ mask,
    const int* __restrict__ q_nb, const int* __restrict__ s_nb,
    const int* __restrict__ u_nb, const int* __restrict__ q_nb2,
    const float* __restrict__ emb_q, const float* __restrict__ emb_q2,
    const float* __restrict__ emb_s, const float* __restrict__ emb_u,
    const float* __restrict__ agg_w, const float* __restrict__ agg_b,
    const float* __restrict__ W_last, const float* __restrict__ b_last) {
    int t = blockIdx.x, b = blockIdx.y, side = blockIdx.z, tid = threadIdx.x;
    int qt = question[b * TT + t];
    float* out = &g_eagg[side][b][t][0];
    if (mask[b * TT + t] == 0) {
        const float* src = side ? emb_q2 + (size_t)qt * DD : emb_q + (size_t)qt * DD;
        for (int d = tid; d < DD; d += 256) out[d] = src[d];
        return;
    }
    extern __shared__ float sm[];
    float* W1  = sm;           // 10100 transposed stride-101
    float* W2  = W1 + 10100;   // 10100
    float* e2  = W2 + 10100;   // 3600
    float* e1  = e2 + 3600;    // 600
    float* e1b = e1 + 600;     // 600
    float* s6  = e1b + 600;    // 600
    float* sb  = s6 + 600;     // 400
    float* e0  = sb + 400;     // 100
    float* e0b = e0 + 100;     // 100
    float* e0c = e0b + 100;    // 100
    float* s1  = e0c + 100;    // 100
    int* sn1 = (int*)(s1 + 100); // 8
    int* sn2 = sn1 + 8;          // 40
    int* sn3 = sn2 + 40;         // 216

    int n0 = side ? user[b * TT + t] : qt;
    const int* tA = side ? u_nb : q_nb;
    const int* tB = side ? q_nb2 : s_nb;
    const float* eE = side ? emb_u : emb_q;    // even hops
    const float* eO = side ? emb_q2 : emb_s;   // odd hops
    const float* b0 = agg_b; const float* b1 = agg_b + DD; const float* b2 = agg_b + 2 * DD;

    for (int i = tid; i < 10000; i += 256) {
        int d = i / 100, k = i % 100;
        W1[k * 101 + d] = agg_w[10000 + i];
        W2[k * 101 + d] = agg_w[20000 + i];
    }
    if (tid < NBR) sn1[tid] = tA[n0 * NBR + tid];
    for (int d = tid; d < 100; d += 256) e0[d] = eE[(size_t)n0 * DD + d];
    __syncthreads();
    if (tid < 36) sn2[tid] = tB[sn1[tid / 6] * NBR + tid % 6];
    for (int i = tid; i < 600; i += 256)
        e1[i] = eO[(size_t)sn1[i / 100] * DD + i % 100];
    __syncthreads();
    if (tid < 216) sn3[tid] = tA[sn2[tid / 6] * NBR + tid % 6];
    for (int i = tid; i < 3600; i += 256)
        e2[i] = eE[(size_t)sn2[i / 100] * DD + i % 100];
    __syncthreads();

    // ---- i=0, j=0 : e0b = tanh((mean(e1)+e0)@W0^T + b0)
    if (tid < 100) {
        float s = 0.f;
        for (int r = 0; r < 6; r++) s += e1[r * 100 + tid];
        s1[tid] = s * (1.f / 6.f) + e0[tid];
    }
    __syncthreads();
    if (tid < 100) {
        float a = b0[tid]; const float* w = agg_w + tid * 100;
#pragma unroll 4
        for (int k = 0; k < 100; k++) a += s1[k] * w[k];
        e0b[tid] = tanhf(a);
    }
    // ---- i=0, j=1 : e1b = tanh((groupmean(e2)+e1)@W1^T + b1)
    for (int i = tid; i < 600; i += 256) {
        int r = i / 100, d = i % 100;
        float s = 0.f;
        for (int r2 = 0; r2 < 6; r2++) s += e2[(r * 6 + r2) * 100 + d];
        s6[i] = s * (1.f / 6.f) + e1[i];
    }
    __syncthreads();
    for (int i = tid; i < 600; i += 256) {
        int r = i / 100, d = i % 100;
        float a = b1[d];
#pragma unroll 4
        for (int k = 0; k < 100; k++) a += s6[r * 100 + k] * W1[k * 101 + d];
        e1b[i] = tanhf(a);
    }
    __syncthreads();
    // ---- i=0, j=2 : e2 = tanh((hop3mean+e2)@W2^T + b2), 36 rows, groups of 4
    for (int g0 = 0; g0 < 36; g0 += 4) {
        for (int i = tid; i < 400; i += 256) {
            int hh = i / 100, d = i % 100; int g = g0 + hh;
            float s = 0.f;
#pragma unroll
            for (int r = 0; r < 6; r++) s += eO[(size_t)sn3[g * 6 + r] * DD + d];
            sb[i] = s * (1.f / 6.f) + e2[g * 100 + d];
        }
        __syncthreads();
        for (int i = tid; i < 400; i += 256) {
            int hh = i / 100, d = i % 100;
            float a = b2[d];
#pragma unroll 4
            for (int k = 0; k < 100; k++) a += sb[hh * 100 + k] * W2[k * 101 + d];
            e2[(g0 + hh) * 100 + d] = tanhf(a);
        }
        __syncthreads();
    }
    // ---- i=1, j=0 : e0c = tanh((mean(e1b)+e0b)@W0^T + b0)
    if (tid < 100) {
        float s = 0.f;
        for (int r = 0; r < 6; r++) s += e1b[r * 100 + tid];
        s1[tid] = s * (1.f / 6.f) + e0b[tid];
    }
    __syncthreads();
    if (tid < 100) {
        float a = b0[tid]; const float* w = agg_w + tid * 100;
#pragma unroll 4
        for (int k = 0; k < 100; k++) a += s1[k] * w[k];
        e0c[tid] = tanhf(a);
    }
    // ---- i=1, j=1 : e1 = tanh((groupmean(new e2)+e1b)@W1^T + b1)
    for (int i = tid; i < 600; i += 256) {
        int r = i / 100, d = i % 100;
        float s = 0.f;
        for (int r2 = 0; r2 < 6; r2++) s += e2[(r * 6 + r2) * 100 + d];
        s6[i] = s * (1.f / 6.f) + e1b[i];
    }
    __syncthreads();
    for (int i = tid; i < 600; i += 256) {
        int r = i / 100, d = i % 100;
        float a = b1[d];
#pragma unroll 4
        for (int k = 0; k < 100; k++) a += s6[r * 100 + k] * W1[k * 101 + d];
        e1[i] = tanhf(a);
    }
    __syncthreads();
    // ---- i=2, j=0 : e0 = tanh((mean(e1)+e0c)@W0^T + b0)
    if (tid < 100) {
        float s = 0.f;
        for (int r = 0; r < 6; r++) s += e1[r * 100 + tid];
        s1[tid] = s * (1.f / 6.f) + e0c[tid];
    }
    __syncthreads();
    if (tid < 100) {
        float a = b0[tid]; const float* w = agg_w + tid * 100;
#pragma unroll 4
        for (int k = 0; k < 100; k++) a += s1[k] * w[k];
        e0[tid] = tanhf(a);
    }
    __syncthreads();
    // ---- final: out = tanh(e0 @ W_last^T + b_last)
    if (tid < 100) {
        float a = b_last[tid]; const float* w = W_last + tid * 100;
#pragma unroll 4
        for (int k = 0; k < 100; k++) a += e0[k] * w[k];
        out[tid] = tanhf(a);
    }
}

// ---------------- C: qs_concat / collapsed ql / static top-k ----------------
__global__ __launch_bounds__(128) void prep_kernel(
    const int* __restrict__ question, const int* __restrict__ qs_index,
    const float* __restrict__ emb_q, const float* __restrict__ emb_s) {
    int t = blockIdx.x, b = blockIdx.y, tid = threadIdx.x;
    __shared__ float qsm[500];
    __shared__ float sc[TS];
    int qn = question[b * TT + t + 1];
    for (int i = tid; i < 500; i += 128) {
        int q = i / 100, d = i % 100;
        float v = (q == 0) ? emb_q[(size_t)qn * DD + d]
                           : emb_s[(size_t)qs_index[qn * SPQ + q - 1] * DD + d];
        qsm[i] = v;
        g_qsc[b][t][q][d] = v;
    }
    __syncthreads();
    if (tid < 5) {
        float a = g_cq;
        for (int d = 0; d < 100; d++) a += qsm[tid * 100 + d] * g_vq[d];
        g_ql[b][t][tid] = a;
    }
    for (int i = tid; i < t; i += 128) {
        const float* er = emb_q + (size_t)question[b * TT + i] * DD;
        float a = 0.f;
#pragma unroll 4
        for (int d = 0; d < 100; d++) a += er[d] * qsm[d];
        sc[i] = a;
    }
    __syncthreads();
    if (tid == 0) {  // exact stable top-k over valid positions i < t
        unsigned long long used = 0ULL;
        for (int s = 0; s < RK; s++) {
            float best = -1e38f; int bi = -1;
            for (int i = 0; i < t; i++)
                if (!((used >> i) & 1ULL) && sc[i] > best) { best = sc[i]; bi = i; }
            if (bi >= 0) { g_idx[b][t][s] = bi; g_sval[b][t][s] = 1; used |= 1ULL << bi; }
            else         { g_idx[b][t][s] = 0;  g_sval[b][t][s] = 0; }
        }
    }
}

// ---------------- D1: fusion e_t for all t (per-b CTA) ----------------
__global__ __launch_bounds__(256) void fusion_et_kernel(
    const int* __restrict__ response, const float* __restrict__ w1p,
    const float* __restrict__ w2p, const float* __restrict__ W_fusion) {
    int b = blockIdx.x, tid = threadIdx.x;
    extern __shared__ float sm[];
    float* WfT = sm;           // 10100
    float* eh  = WfT + 10100;  // 4900
    for (int i = tid; i < 10000; i += 256) {
        int d = i / 100, k = i % 100;
        WfT[k * 101 + d] = W_fusion[d * 200 + k];
    }
    float w1 = *w1p, w2 = *w2p;
    for (int i = tid; i < 4900; i += 256) {
        int t = i / 100, d = i % 100;
        eh[i] = w1 * g_eagg[0][b][t][d] + w2 * g_eagg[1][b][t][d];
    }
    __syncthreads();
    for (int i = tid; i < 4900; i += 256) {
        int t = i / 100, d = i % 100;
        float a = g_resp[response[b * TT + t]][d];
#pragma unroll 4
        for (int k = 0; k < 100; k++) a += eh[t * 100 + k] * WfT[k * 101 + d];
        g_et[b][t][d] = fmaxf(a, 0.f);
    }
}

// ---------------- D2: input-part of LSTM gates ----------------
__global__ __launch_bounds__(256) void gates_kernel(
    const float* __restrict__ W_ih, const float* __restrict__ b_ih,
    const float* __restrict__ b_hh) {
    int j0 = blockIdx.x * 100, b = blockIdx.y, tid = threadIdx.x;
    extern __shared__ float sm[];
    float* WT = sm;          // 10100
    float* et = WT + 10100;  // 4900
    for (int i = tid; i < 10000; i += 256) {
        int jj = i / 100, k = i % 100;
        WT[k * 101 + jj] = W_ih[(j0 + jj) * 100 + k];
    }
    for (int i = tid; i < 4900; i += 256) et[i] = (&g_et[b][0][0])[i];
    __syncthreads();
    for (int i = tid; i < 4900; i += 256) {
        int t = i / 100, jj = i % 100;
        float a = b_ih[j0 + jj] + b_hh[j0 + jj];
#pragma unroll 4
        for (int k = 0; k < 100; k++) a += et[t * 100 + k] * WT[k * 101 + jj];
        g_gates[b][t][j0 + jj] = a;
    }
}

// ---------------- E: per-batch sequential LSTM + attention ----------------
__global__ __launch_bounds__(256) void scan_kernel(
    const int* __restrict__ mask, const float* __restrict__ W_hh,
    const float* __restrict__ b_w, float* __restrict__ out) {
    int b = blockIdx.x, tid = threadIdx.x;
    extern __shared__ float sm[];
    float* WhhT = sm;             // 40100
    float* sh   = WhhT + 40100;   // 4900
    float* gates = sh + 4900;     // 400
    float* h    = gates + 400;    // 100
    float* c    = h + 100;        // 100
    float* qsm  = c + 100;        // 500
    float* gbuf = qsm + 500;      // 64
    float* lbuf = gbuf + 64;      // 64
    float* klb  = lbuf + 64;      // 16
    float* vks  = klb + 16;       // 100
    float* sql  = vks + 100;      // 8
    float* red  = sql + 8;        // 4
    int* sidx = (int*)(red + 4);  // 16
    int* ssv  = sidx + 16;        // 16

    for (int i = tid; i < 40000; i += 256)
        WhhT[(i % 100) * 401 + i / 100] = W_hh[i];
    for (int i = tid; i < 100; i += 256) { h[i] = 0.f; c[i] = 0.f; vks[i] = g_vk[i]; }
    if (tid == 0) { out[b * TT] = 0.5f; red[2] = g_ck + b_w[0]; }
    __syncthreads();

    for (int t = 0; t < TS; t++) {
        for (int i = tid; i < 500; i += 256) qsm[i] = (&g_qsc[b][t][0][0])[i];
        if (tid < RK) { sidx[tid] = g_idx[b][t][tid]; ssv[tid] = g_sval[b][t][tid]; }
        else if (tid < RK + 5) sql[tid - RK] = g_ql[b][t][tid - RK];
        for (int j = tid; j < 400; j += 256) {
            float a = g_gates[b][t][j];
#pragma unroll 4
            for (int d = 0; d < 100; d++) a += h[d] * WhhT[d * 401 + j];
            gates[j] = a;
        }
        __syncthreads();
        int mv = mask[b * TT + t];
        if (tid < 100) {
            float gi = gates[tid], gf = gates[100 + tid], gg = gates[200 + tid],
                  go = gates[300 + tid];
            float si = 1.f / (1.f + expf(-gi));
            float sf = 1.f / (1.f + expf(-gf));
            float so = 1.f / (1.f + expf(-go));
            float c2 = sf * c[tid] + si * tanhf(gg);
            float h2 = so * tanhf(c2);
            if (mv) { h[tid] = h2; c[tid] = c2; }
            sh[t * 100 + tid] = h[tid];
        }
        __syncthreads();
        if (tid < 55) {
            int q = tid / 11, s = tid % 11;
            const float* sr = (s == 0) ? h : (ssv[s - 1] ? sh + sidx[s - 1] * 100 : (float*)0);
            float a = 0.f;
            if (sr) {
                const float* qr = qsm + q * 100;
#pragma unroll 4
                for (int d = 0; d < 100; d++) a += qr[d] * sr[d];
            }
            gbuf[tid] = a;
        } else if (tid < 66) {
            int s = tid - 55;
            const float* sr = (s == 0) ? h : (ssv[s - 1] ? sh + sidx[s - 1] * 100 : (float*)0);
            float a = -1e30f;
            if (sr) {
                a = red[2];
#pragma unroll 4
                for (int d = 0; d < 100; d++) a += sr[d] * vks[d];
            }
            klb[s] = a;
        }
        __syncthreads();
        if (tid < 64) lbuf[tid] = (tid < 55) ? sql[tid / 11] + klb[tid % 11] : -1e30f;
        __syncthreads();
        if (tid < 32) {
            float mx = fmaxf(lbuf[tid], lbuf[tid + 32]);
            for (int o = 16; o > 0; o >>= 1)
                mx = fmaxf(mx, __shfl_xor_sync(0xffffffffu, mx, o));
            if (tid == 0) red[0] = mx;
        }
        __syncthreads();
        if (tid < 64) {
            float e = (tid < 55) ? expf(lbuf[tid] - red[0]) : 0.f;
            lbuf[tid] = e;
            gbuf[tid] = (tid < 55) ? gbuf[tid] * e : 0.f;
        }
        __syncthreads();
        if (tid < 32) {
            float se = lbuf[tid] + lbuf[tid + 32];
            float sp = gbuf[tid] + gbuf[tid + 32];
            for (int o = 16; o > 0; o >>= 1) {
                se += __shfl_xor_sync(0xffffffffu, se, o);
                sp += __shfl_xor_sync(0xffffffffu, sp, o);
            }
            if (tid == 0) out[b * TT + t + 1] = 1.f / (1.f + expf(-sp / se));
        }
        __syncthreads();
    }
}

// ---------------- launch ----------------
extern "C" void kernel_launch(void* const* d_in, const int* in_sizes, int n_in,
                              void* d_out, int out_size) {
    const int* user      = (const int*)d_in[0];
    const int* question  = (const int*)d_in[1];
    const int* response  = (const int*)d_in[2];
    const int* mask      = (const int*)d_in[3];
    const int* q_nb      = (const int*)d_in[4];
    const int* s_nb      = (const int*)d_in[5];
    const int* u_nb      = (const int*)d_in[6];
    const int* q_nb2     = (const int*)d_in[7];
    const int* qs_index  = (const int*)d_in[8];
    const float* emb_q   = (const float*)d_in[9];
    const float* emb_q2  = (const float*)d_in[10];
    const float* emb_s   = (const float*)d_in[11];
    const float* emb_u   = (const float*)d_in[12];
    const float* emb_r   = (const float*)d_in[13];
    const float* w1      = (const float*)d_in[14];
    const float* w2      = (const float*)d_in[15];
    const float* W_ih    = (const float*)d_in[16];
    const float* W_hh    = (const float*)d_in[17];
    const float* b_ih    = (const float*)d_in[18];
    const float* b_hh    = (const float*)d_in[19];
    const float* agg_w   = (const float*)d_in[20];
    const float* agg_b   = (const float*)d_in[21];
    const float* W_al    = (const float*)d_in[22];
    const float* b_al    = (const float*)d_in[23];
    const float* W_query = (const float*)d_in[24];
    const float* b_query = (const float*)d_in[25];
    const float* W_key   = (const float*)d_in[26];
    const float* b_key   = (const float*)d_in[27];
    const float* W_w     = (const float*)d_in[28];
    const float* b_w     = (const float*)d_in[29];
    const float* W_fus   = (const float*)d_in[30];
    const float* b_fus   = (const float*)d_in[31];
    float* out = (float*)d_out;

    const size_t agg_sm  = 26400 * 4 + 264 * 4;   // 106656 B
    const size_t fus_sm  = 15000 * 4;             // 60000 B
    const size_t scan_sm = 46356 * 4 + 32 * 4;    // 185552 B
    cudaFuncSetAttribute(agg_kernel, cudaFuncAttributeMaxDynamicSharedMemorySize, (int)agg_sm);
    cudaFuncSetAttribute(fusion_et_kernel, cudaFuncAttributeMaxDynamicSharedMemorySize, (int)fus_sm);
    cudaFuncSetAttribute(gates_kernel, cudaFuncAttributeMaxDynamicSharedMemorySize, (int)fus_sm);
    cudaFuncSetAttribute(scan_kernel, cudaFuncAttributeMaxDynamicSharedMemorySize, (int)scan_sm);

    precompute_kernel<<<1, 128>>>(W_query, b_query, W_key, b_key, W_w, emb_r, W_fus, b_fus);
    agg_kernel<<<dim3(TS, TB, 2), 256, agg_sm>>>(user, question, mask, q_nb, s_nb,
                                                 u_nb, q_nb2, emb_q, emb_q2, emb_s,
                                                 emb_u, agg_w, agg_b, W_al, b_al);
    prep_kernel<<<dim3(TS, TB), 128>>>(question, qs_index, emb_q, emb_s);
    fusion_et_kernel<<<TB, 256, fus_sm>>>(response, w1, w2, W_fus);
    gates_kernel<<<dim3(4, TB), 256, fus_sm>>>(W_ih, b_ih, b_hh);
    scan_kernel<<<TB, 256, scan_sm>>>(mask, W_hh, b_w, out);
}

// round 3
// speedup vs baseline: 1.4203x; 1.4203x over previous
#include <cuda_runtime.h>

#define TB 32
#define TT 50
#define TS 49
#define DD 100
#define NBR 6
#define SPQ 4
#define RK 10

// ---------------- device scratch ----------------
__device__ float g_eagg[2][TB][TS][DD];
__device__ float g_et[TB][TS][DD];
__device__ float g_gates[TB][TS][4 * DD];
__device__ float g_qsc[TB][TS][5][DD];
__device__ float g_ql[TB][TS][5];
__device__ float g_h[TB][TS][DD];
__device__ int   g_idx[TB][TS][RK];
__device__ int   g_sval[TB][TS][RK];
__device__ float g_vq[DD], g_vk[DD];
__device__ float g_cq, g_ck;
__device__ float g_resp[2][DD];

#define FMA4(ac, a, w) { ac.x += (a) * (w).x; ac.y += (a) * (w).y; ac.z += (a) * (w).z; ac.w += (a) * (w).w; }

// ---------------- A: collapsed projections (grid 4) ----------------
__global__ void precompute_kernel(const float* __restrict__ W_query,
                                  const float* __restrict__ b_query,
                                  const float* __restrict__ W_key,
                                  const float* __restrict__ b_key,
                                  const float* __restrict__ W_w,
                                  const float* __restrict__ emb_r,
                                  const float* __restrict__ W_fusion,
                                  const float* __restrict__ b_fusion) {
    int blk = blockIdx.x, tid = threadIdx.x;
    if (blk == 0) {
        for (int k = tid; k < DD; k += 128) {
            float a = 0.f;
            for (int d = 0; d < DD; d++) a += W_query[d * DD + k] * W_w[d];
            g_vq[k] = a;
        }
        if (tid == 0) {
            float c = 0.f;
            for (int d = 0; d < DD; d++) c += b_query[d] * W_w[d];
            g_cq = c;
        }
    } else if (blk == 1) {
        for (int k = tid; k < DD; k += 128) {
            float a = 0.f;
            for (int d = 0; d < DD; d++) a += W_key[d * DD + k] * W_w[DD + d];
            g_vk[k] = a;
        }
        if (tid == 0) {
            float c = 0.f;
            for (int d = 0; d < DD; d++) c += b_key[d] * W_w[DD + d];
            g_ck = c;
        }
    } else {
        int r = blk - 2;
        for (int d = tid; d < DD; d += 128) {
            float a = b_fusion[d];
            for (int k = 0; k < DD; k++)
                a += emb_r[r * DD + k] * W_fusion[d * 2 * DD + DD + k];
            g_resp[r][d] = a;
        }
    }
}

// warp-cooperative 100x100 matvec: out[d]=tanh(sum_k in[k]*Wg[d*100+k]+bg[d])
__device__ __forceinline__ void mv100(const float* __restrict__ in,
                                      const float* __restrict__ Wg,
                                      const float* __restrict__ bg,
                                      float* out, int tid) {
    int w = tid >> 5, l = tid & 31;
    for (int d = w; d < 100; d += 8) {
        float p = 0.f;
        for (int k = l; k < 100; k += 32) p += in[k] * Wg[d * 100 + k];
        for (int o = 16; o > 0; o >>= 1) p += __shfl_xor_sync(0xffffffffu, p, o);
        if (l == 0) out[d] = tanhf(p + bg[d]);
    }
}

// 6x100 matmul, 2x2 reg tiles, 150 threads: out = tanh(in @ W1T + b1)
__device__ __forceinline__ void mm6(const float* __restrict__ in,
                                    const float* __restrict__ W1T,
                                    const float* __restrict__ b1g,
                                    float* out, int tid) {
    if (tid < 150) {
        int r0 = (tid / 50) * 2, d0 = (tid % 50) * 2;
        float a00 = 0.f, a01 = 0.f, a10 = 0.f, a11 = 0.f;
#pragma unroll 4
        for (int k = 0; k < 100; k++) {
            float2 w = *(const float2*)&W1T[k * 100 + d0];
            float x0 = in[r0 * 100 + k], x1 = in[r0 * 100 + 100 + k];
            a00 += x0 * w.x; a01 += x0 * w.y;
            a10 += x1 * w.x; a11 += x1 * w.y;
        }
        float b0 = b1g[d0], b1 = b1g[d0 + 1];
        out[r0 * 100 + d0] = tanhf(a00 + b0);
        out[r0 * 100 + d0 + 1] = tanhf(a01 + b1);
        out[r0 * 100 + 100 + d0] = tanhf(a10 + b0);
        out[r0 * 100 + 100 + d0 + 1] = tanhf(a11 + b1);
    }
}

// ---------------- B: graph aggregation ----------------
__global__ __launch_bounds__(256) void agg_kernel(
    const int* __restrict__ user, const int* __restrict__ question,
    const int* __restrict__ mask,
    const int* __restrict__ q_nb, const int* __restrict__ s_nb,
    const int* __restrict__ u_nb, const int* __restrict__ q_nb2,
    const float* __restrict__ emb_q, const float* __restrict__ emb_q2,
    const float* __restrict__ emb_s, const float* __restrict__ emb_u,
    const float* __restrict__ agg_w, const float* __restrict__ agg_b,
    const float* __restrict__ W_last, const float* __restrict__ b_last) {
    int t = blockIdx.x, b = blockIdx.y, side = blockIdx.z, tid = threadIdx.x;
    int qt = question[b * TT + t];
    float* outg = &g_eagg[side][b][t][0];
    if (mask[b * TT + t] == 0) {
        const float* src = side ? emb_q2 + (size_t)qt * DD : emb_q + (size_t)qt * DD;
        for (int d = tid; d < DD; d += 256) outg[d] = src[d];
        return;
    }
    extern __shared__ float sm[];
    float* W1T = sm;            // 10000, W1T[k*100+d]
    float* W2T = W1T + 10000;   // 10000
    float* e2s = W2T + 10000;   // 3600
    float* e1  = e2s + 3600;    // 600
    float* e1b = e1 + 600;      // 600
    float* s6  = e1b + 600;     // 600
    float* e0v = s6 + 600;      // 100
    float* e0b = e0v + 100;     // 100
    float* e0c = e0b + 100;     // 100
    float* s1  = e0c + 100;     // 100
    int* sn1 = (int*)(s1 + 100);
    int* sn2 = sn1 + 8;
    int* sn3 = sn2 + 36;

    int n0 = side ? user[b * TT + t] : qt;
    const int* tA = side ? u_nb : q_nb;
    const int* tB = side ? q_nb2 : s_nb;
    const float* eE = side ? emb_u : emb_q;
    const float* eO = side ? emb_q2 : emb_s;
    const float* b0g = agg_b;
    const float* b1g = agg_b + DD;
    const float* b2g = agg_b + 2 * DD;
    const float* W0g = agg_w;

    for (int i = tid; i < 10000; i += 256) {
        int d = i / 100, k = i % 100;
        W1T[k * 100 + d] = agg_w[10000 + i];
        W2T[k * 100 + d] = agg_w[20000 + i];
    }
    if (tid < NBR) sn1[tid] = tA[n0 * NBR + tid];
    for (int d = tid; d < 100; d += 256) e0v[d] = eE[(size_t)n0 * DD + d];
    __syncthreads();
    if (tid < 36) sn2[tid] = tB[sn1[tid / 6] * NBR + tid % 6];
    for (int i = tid; i < 600; i += 256)
        e1[i] = eO[(size_t)sn1[i / 100] * DD + i % 100];
    __syncthreads();
    if (tid < 216) sn3[tid] = tA[sn2[tid / 6] * NBR + tid % 6];
    for (int i = tid; i < 3600; i += 256)
        e2s[i] = eE[(size_t)sn2[i / 100] * DD + i % 100];
    __syncthreads();
    // means of originals
    for (int i = tid; i < 600; i += 256) {
        int r = i / 100, d = i % 100;
        float s = 0.f;
        for (int r2 = 0; r2 < 6; r2++) s += e2s[(r * 6 + r2) * 100 + d];
        s6[i] = s * (1.f / 6.f) + e1[i];
    }
    if (tid < 100) {
        float s = 0.f;
        for (int r = 0; r < 6; r++) s += e1[r * 100 + tid];
        s1[tid] = s * (1.f / 6.f) + e0v[tid];
    }
    __syncthreads();
    mv100(s1, W0g, b0g, e0b, tid);  // i=0 j=0
    // stage hop3 means in-place: e2s += mean3
    for (int i = tid; i < 3600; i += 256) {
        int g = i / 100, d = i % 100;
        float s = 0.f;
#pragma unroll
        for (int r = 0; r < 6; r++) s += eO[(size_t)sn3[g * 6 + r] * DD + d];
        e2s[i] += s * (1.f / 6.f);
    }
    __syncthreads();
    // i=0 j=2 : 36x100, 4x4 reg tiles, in-place (barrier between read & write)
    float4 ac0, ac1, ac2, ac3;
    int r0 = 0, d0 = 0;
    if (tid < 225) {
        r0 = (tid / 25) * 4; d0 = (tid % 25) * 4;
        ac0 = make_float4(0, 0, 0, 0); ac1 = ac0; ac2 = ac0; ac3 = ac0;
#pragma unroll 2
        for (int k = 0; k < 100; k++) {
            float4 w = *(const float4*)&W2T[k * 100 + d0];
            float x0 = e2s[r0 * 100 + k];
            float x1 = e2s[r0 * 100 + 100 + k];
            float x2 = e2s[r0 * 100 + 200 + k];
            float x3 = e2s[r0 * 100 + 300 + k];
            FMA4(ac0, x0, w); FMA4(ac1, x1, w); FMA4(ac2, x2, w); FMA4(ac3, x3, w);
        }
    }
    __syncthreads();
    if (tid < 225) {
        float bb0 = b2g[d0], bb1 = b2g[d0 + 1], bb2 = b2g[d0 + 2], bb3 = b2g[d0 + 3];
        float* o0 = e2s + r0 * 100 + d0;
        o0[0] = tanhf(ac0.x + bb0); o0[1] = tanhf(ac0.y + bb1); o0[2] = tanhf(ac0.z + bb2); o0[3] = tanhf(ac0.w + bb3);
        o0[100] = tanhf(ac1.x + bb0); o0[101] = tanhf(ac1.y + bb1); o0[102] = tanhf(ac1.z + bb2); o0[103] = tanhf(ac1.w + bb3);
        o0[200] = tanhf(ac2.x + bb0); o0[201] = tanhf(ac2.y + bb1); o0[202] = tanhf(ac2.z + bb2); o0[203] = tanhf(ac2.w + bb3);
        o0[300] = tanhf(ac3.x + bb0); o0[301] = tanhf(ac3.y + bb1); o0[302] = tanhf(ac3.z + bb2); o0[303] = tanhf(ac3.w + bb3);
    }
    mm6(s6, W1T, b1g, e1b, tid);    // i=0 j=1 (reads s6, independent of e2s)
    __syncthreads();
    // second-level means (new e2) + s1
    for (int i = tid; i < 600; i += 256) {
        int r = i / 100, d = i % 100;
        float s = 0.f;
        for (int r2 = 0; r2 < 6; r2++) s += e2s[(r * 6 + r2) * 100 + d];
        s6[i] = s * (1.f / 6.f) + e1b[i];
    }
    if (tid < 100) {
        float s = 0.f;
        for (int r = 0; r < 6; r++) s += e1b[r * 100 + tid];
        s1[tid] = s * (1.f / 6.f) + e0b[tid];
    }
    __syncthreads();
    mv100(s1, W0g, b0g, e0c, tid);  // i=1 j=0
    mm6(s6, W1T, b1g, e1, tid);     // i=1 j=1
    __syncthreads();
    if (tid < 100) {
        float s = 0.f;
        for (int r = 0; r < 6; r++) s += e1[r * 100 + tid];
        s1[tid] = s * (1.f / 6.f) + e0c[tid];
    }
    __syncthreads();
    mv100(s1, W0g, b0g, e0v, tid);  // i=2 j=0
    __syncthreads();
    mv100(e0v, W_last, b_last, outg, tid);  // final
}

// ---------------- C: qs_concat / ql / static top-k ----------------
__global__ __launch_bounds__(128) void prep_kernel(
    const int* __restrict__ question, const int* __restrict__ qs_index,
    const float* __restrict__ emb_q, const float* __restrict__ emb_s) {
    int t = blockIdx.x, b = blockIdx.y, tid = threadIdx.x;
    __shared__ float qsm[500];
    __shared__ float sc[TS];
    int qn = question[b * TT + t + 1];
    for (int i = tid; i < 500; i += 128) {
        int q = i / 100, d = i % 100;
        float v = (q == 0) ? emb_q[(size_t)qn * DD + d]
                           : emb_s[(size_t)qs_index[qn * SPQ + q - 1] * DD + d];
        qsm[i] = v;
        g_qsc[b][t][q][d] = v;
    }
    __syncthreads();
    if (tid < 5) {
        float a = g_cq;
        for (int d = 0; d < 100; d++) a += qsm[tid * 100 + d] * g_vq[d];
        g_ql[b][t][tid] = a;
    }
    for (int i = tid; i < t; i += 128) {
        const float* er = emb_q + (size_t)question[b * TT + i] * DD;
        float a = 0.f;
#pragma unroll 4
        for (int d = 0; d < 100; d++) a += er[d] * qsm[d];
        sc[i] = a;
    }
    __syncthreads();
    if (tid == 0) {
        unsigned long long used = 0ULL;
        for (int s = 0; s < RK; s++) {
            float best = -1e38f; int bi = -1;
            for (int i = 0; i < t; i++)
                if (!((used >> i) & 1ULL) && sc[i] > best) { best = sc[i]; bi = i; }
            if (bi >= 0) { g_idx[b][t][s] = bi; g_sval[b][t][s] = 1; used |= 1ULL << bi; }
            else         { g_idx[b][t][s] = 0;  g_sval[b][t][s] = 0; }
        }
    }
}

// ---------------- D1: fusion e_t ----------------
__global__ __launch_bounds__(512) void fusion_et_kernel(
    const int* __restrict__ response, const float* __restrict__ w1p,
    const float* __restrict__ w2p, const float* __restrict__ W_fusion) {
    int b = blockIdx.x, tid = threadIdx.x;
    extern __shared__ float sm[];
    float* WT = sm;          // 10000
    float* eh = WT + 10000;  // 5200
    for (int i = tid; i < 10000; i += 512) {
        int d = i / 100, k = i % 100;
        WT[k * 100 + d] = W_fusion[d * 200 + k];
    }
    float w1 = *w1p, w2 = *w2p;
    for (int i = tid; i < 5200; i += 512)
        eh[i] = (i < 4900) ? w1 * g_eagg[0][b][i / 100][i % 100] +
                             w2 * g_eagg[1][b][i / 100][i % 100]
                           : 0.f;
    __syncthreads();
    if (tid < 325) {
        int t0 = (tid / 25) * 4, d0 = (tid % 25) * 4;
        float4 ac0 = make_float4(0, 0, 0, 0), ac1 = ac0, ac2 = ac0, ac3 = ac0;
#pragma unroll 2
        for (int k = 0; k < 100; k++) {
            float4 w = *(const float4*)&WT[k * 100 + d0];
            float x0 = eh[t0 * 100 + k], x1 = eh[t0 * 100 + 100 + k];
            float x2 = eh[t0 * 100 + 200 + k], x3 = eh[t0 * 100 + 300 + k];
            FMA4(ac0, x0, w); FMA4(ac1, x1, w); FMA4(ac2, x2, w); FMA4(ac3, x3, w);
        }
        float4 acs[4] = {ac0, ac1, ac2, ac3};
        for (int i = 0; i < 4; i++) {
            int t = t0 + i;
            if (t < TS) {
                int r = response[b * TT + t];
                g_et[b][t][d0]     = fmaxf(acs[i].x + g_resp[r][d0], 0.f);
                g_et[b][t][d0 + 1] = fmaxf(acs[i].y + g_resp[r][d0 + 1], 0.f);
                g_et[b][t][d0 + 2] = fmaxf(acs[i].z + g_resp[r][d0 + 2], 0.f);
                g_et[b][t][d0 + 3] = fmaxf(acs[i].w + g_resp[r][d0 + 3], 0.f);
            }
        }
    }
}

// ---------------- D2: input part of gates ----------------
__global__ __launch_bounds__(512) void gates_kernel(
    const float* __restrict__ W_ih, const float* __restrict__ b_ih,
    const float* __restrict__ b_hh) {
    int jc = blockIdx.x, b = blockIdx.y, tid = threadIdx.x;
    extern __shared__ float sm[];
    float* WT = sm;          // 10000
    float* et = WT + 10000;  // 5200
    for (int i = tid; i < 10000; i += 512) {
        int jj = i / 100, k = i % 100;
        WT[k * 100 + jj] = W_ih[(jc * 100 + jj) * 100 + k];
    }
    for (int i = tid; i < 5200; i += 512)
        et[i] = (i < 4900) ? g_et[b][i / 100][i % 100] : 0.f;
    __syncthreads();
    if (tid < 325) {
        int t0 = (tid / 25) * 4, j0 = (tid % 25) * 4;
        float4 ac0 = make_float4(0, 0, 0, 0), ac1 = ac0, ac2 = ac0, ac3 = ac0;
#pragma unroll 2
        for (int k = 0; k < 100; k++) {
            float4 w = *(const float4*)&WT[k * 100 + j0];
            float x0 = et[t0 * 100 + k], x1 = et[t0 * 100 + 100 + k];
            float x2 = et[t0 * 100 + 200 + k], x3 = et[t0 * 100 + 300 + k];
            FMA4(ac0, x0, w); FMA4(ac1, x1, w); FMA4(ac2, x2, w); FMA4(ac3, x3, w);
        }
        int jg = jc * 100 + j0;
        float bb0 = b_ih[jg] + b_hh[jg], bb1 = b_ih[jg + 1] + b_hh[jg + 1];
        float bb2 = b_ih[jg + 2] + b_hh[jg + 2], bb3 = b_ih[jg + 3] + b_hh[jg + 3];
        float4 acs[4] = {ac0, ac1, ac2, ac3};
        for (int i = 0; i < 4; i++) {
            int t = t0 + i;
            if (t < TS) {
                g_gates[b][t][jg]     = acs[i].x + bb0;
                g_gates[b][t][jg + 1] = acs[i].y + bb1;
                g_gates[b][t][jg + 2] = acs[i].z + bb2;
                g_gates[b][t][jg + 3] = acs[i].w + bb3;
            }
        }
    }
}

// ---------------- E: pure LSTM scan (one CTA per b) ----------------
__global__ __launch_bounds__(128) void scan_kernel(
    const int* __restrict__ mask, const float* __restrict__ W_hh,
    float* __restrict__ out) {
    int b = blockIdx.x, tid = threadIdx.x;
    extern __shared__ float sm[];
    float* WT = sm;           // 100*404, WT[d*404+j]
    float* h  = WT + 40400;   // 100
    float* c  = h + 100;      // 100
    float* gs = c + 100;      // 400
    for (int i = tid; i < 40000; i += 128) {
        int j = i / 100, d = i % 100;
        WT[d * 404 + j] = W_hh[i];
    }
    for (int i = tid; i < 100; i += 128) { h[i] = 0.f; c[i] = 0.f; }
    if (tid == 0) out[b * TT] = 0.5f;
    __syncthreads();
    for (int t = 0; t < TS; t++) {
        if (tid < 100) {
            float4 gin = *(const float4*)&g_gates[b][t][tid * 4];
            float4 ac = make_float4(0, 0, 0, 0);
#pragma unroll 4
            for (int d = 0; d < 100; d++) {
                float hb = h[d];
                float4 w = *(const float4*)&WT[d * 404 + tid * 4];
                FMA4(ac, hb, w);
            }
            gs[tid * 4]     = ac.x + gin.x;
            gs[tid * 4 + 1] = ac.y + gin.y;
            gs[tid * 4 + 2] = ac.z + gin.z;
            gs[tid * 4 + 3] = ac.w + gin.w;
        }
        __syncthreads();
        if (tid < 100) {
            float gi = gs[tid], gf = gs[100 + tid], gg = gs[200 + tid], go = gs[300 + tid];
            float si = 1.f / (1.f + expf(-gi));
            float sf = 1.f / (1.f + expf(-gf));
            float so = 1.f / (1.f + expf(-go));
            float c2 = sf * c[tid] + si * tanhf(gg);
            float h2 = so * tanhf(c2);
            if (mask[b * TT + t]) { h[tid] = h2; c[tid] = c2; }
            g_h[b][t][tid] = h[tid];
        }
        __syncthreads();
    }
}

// ---------------- F: attention readout (fully parallel) ----------------
__global__ __launch_bounds__(128) void attn_kernel(const float* __restrict__ b_w,
                                                   float* __restrict__ out) {
    int t = blockIdx.x, b = blockIdx.y, tid = threadIdx.x;
    __shared__ float st[1100], qsm[500], vks[100], lbuf[64], gbuf[64], klb[16], red[2], sql[5];
    __shared__ int sidx[10], ssv[10];
    if (tid < 10) { sidx[tid] = g_idx[b][t][tid]; ssv[tid] = g_sval[b][t][tid]; }
    if (tid >= 16 && tid < 21) sql[tid - 16] = g_ql[b][t][tid - 16];
    __syncthreads();
    for (int i = tid; i < 1100; i += 128) {
        int s = i / 100, d = i % 100;
        int row = (s == 0) ? t : sidx[s - 1];
        st[i] = g_h[b][row][d];
    }
    for (int i = tid; i < 500; i += 128) qsm[i] = (&g_qsc[b][t][0][0])[i];
    for (int d = tid; d < 100; d += 128) vks[d] = g_vk[d];
    __syncthreads();
    float ckb = g_ck + b_w[0];
    if (tid < 55) {
        int q = tid / 11, s = tid % 11;
        bool v = (s == 0) || ssv[s - 1];
        float a = 0.f;
        if (v) {
            const float* qr = qsm + q * 100;
            const float* sr = st + s * 100;
#pragma unroll 4
            for (int d = 0; d < 100; d++) a += qr[d] * sr[d];
        }
        gbuf[tid] = a;
    } else if (tid < 66) {
        int s = tid - 55;
        bool v = (s == 0) || ssv[s - 1];
        float a = -1e30f;
        if (v) {
            a = ckb;
            const float* sr = st + s * 100;
#pragma unroll 4
            for (int d = 0; d < 100; d++) a += sr[d] * vks[d];
        }
        klb[s] = a;
    }
    __syncthreads();
    if (tid < 64) {
        float lv = (tid < 55) ? sql[tid / 11] + klb[tid % 11] : -1e30f;
        lbuf[tid] = lv;
    }
    __syncthreads();
    if (tid < 32) {
        float mx = fmaxf(lbuf[tid], lbuf[tid + 32]);
        for (int o = 16; o > 0; o >>= 1)
            mx = fmaxf(mx, __shfl_xor_sync(0xffffffffu, mx, o));
        if (tid == 0) red[0] = mx;
    }
    __syncthreads();
    if (tid < 64) {
        float e = (tid < 55) ? expf(lbuf[tid] - red[0]) : 0.f;
        lbuf[tid] = e;
        gbuf[tid] = (tid < 55) ? gbuf[tid] * e : 0.f;
    }
    __syncthreads();
    if (tid < 32) {
        float se = lbuf[tid] + lbuf[tid + 32];
        float sp = gbuf[tid] + gbuf[tid + 32];
        for (int o = 16; o > 0; o >>= 1) {
            se += __shfl_xor_sync(0xffffffffu, se, o);
            sp += __shfl_xor_sync(0xffffffffu, sp, o);
        }
        if (tid == 0) out[b * TT + t + 1] = 1.f / (1.f + expf(-sp / se));
    }
}

// ---------------- launch ----------------
extern "C" void kernel_launch(void* const* d_in, const int* in_sizes, int n_in,
                              void* d_out, int out_size) {
    const int* user      = (const int*)d_in[0];
    const int* question  = (const int*)d_in[1];
    const int* response  = (const int*)d_in[2];
    const int* mask      = (const int*)d_in[3];
    const int* q_nb      = (const int*)d_in[4];
    const int* s_nb      = (const int*)d_in[5];
    const int* u_nb      = (const int*)d_in[6];
    const int* q_nb2     = (const int*)d_in[7];
    const int* qs_index  = (const int*)d_in[8];
    const float* emb_q   = (const float*)d_in[9];
    const float* emb_q2  = (const float*)d_in[10];
    const float* emb_s   = (const float*)d_in[11];
    const float* emb_u   = (const float*)d_in[12];
    const float* emb_r   = (const float*)d_in[13];
    const float* w1      = (const float*)d_in[14];
    const float* w2      = (const float*)d_in[15];
    const float* W_ih    = (const float*)d_in[16];
    const float* W_hh    = (const float*)d_in[17];
    const float* b_ih    = (const float*)d_in[18];
    const float* b_hh    = (const float*)d_in[19];
    const float* agg_w   = (const float*)d_in[20];
    const float* agg_b   = (const float*)d_in[21];
    const float* W_al    = (const float*)d_in[22];
    const float* b_al    = (const float*)d_in[23];
    const float* W_query = (const float*)d_in[24];
    const float* b_query = (const float*)d_in[25];
    const float* W_key   = (const float*)d_in[26];
    const float* b_key   = (const float*)d_in[27];
    const float* W_w     = (const float*)d_in[28];
    const float* b_w     = (const float*)d_in[29];
    const float* W_fus   = (const float*)d_in[30];
    const float* b_fus   = (const float*)d_in[31];
    float* out = (float*)d_out;

    const size_t agg_sm  = 104448;
    const size_t fus_sm  = 15200 * 4;
    const size_t scan_sm = 41000 * 4;
    cudaFuncSetAttribute(agg_kernel, cudaFuncAttributeMaxDynamicSharedMemorySize, (int)agg_sm);
    cudaFuncSetAttribute(fusion_et_kernel, cudaFuncAttributeMaxDynamicSharedMemorySize, (int)fus_sm);
    cudaFuncSetAttribute(gates_kernel, cudaFuncAttributeMaxDynamicSharedMemorySize, (int)fus_sm);
    cudaFuncSetAttribute(scan_kernel, cudaFuncAttributeMaxDynamicSharedMemorySize, (int)scan_sm);

    precompute_kernel<<<4, 128>>>(W_query, b_query, W_key, b_key, W_w, emb_r, W_fus, b_fus);
    agg_kernel<<<dim3(TS, TB, 2), 256, agg_sm>>>(user, question, mask, q_nb, s_nb,
                                                 u_nb, q_nb2, emb_q, emb_q2, emb_s,
                                                 emb_u, agg_w, agg_b, W_al, b_al);
    prep_kernel<<<dim3(TS, TB), 128>>>(question, qs_index, emb_q, emb_s);
    fusion_et_kernel<<<TB, 512, fus_sm>>>(response, w1, w2, W_fus);
    gates_kernel<<<dim3(4, TB), 512, fus_sm>>>(W_ih, b_ih, b_hh);
    scan_kernel<<<TB, 128, scan_sm>>>(mask, W_hh, out);
    attn_kernel<<<dim3(TS, TB), 128>>>(b_w, out);
}

// round 4
// speedup vs baseline: 1.5380x; 1.0828x over previous
#include <cuda_runtime.h>

#define TB 32
#define TT 50
#define TS 49
#define DD 100
#define NBR 6
#define SPQ 4
#define RK 10

// ---------------- device scratch ----------------
__device__ float g_eagg[2][TB][TS][DD];
__device__ float g_et[TB][TS][DD];
__device__ float g_gates[TB][TS][4 * DD];
__device__ float g_qsc[TB][TS][5][DD];
__device__ float g_ql[TB][TS][5];
__device__ float g_h[TB][TS][DD];
__device__ int   g_idx[TB][TS][RK];
__device__ int   g_sval[TB][TS][RK];
__device__ float g_vq[DD], g_vk[DD];
__device__ float g_cq, g_ck;
__device__ float g_resp[2][DD];

#define FMA4(ac, a, w) { ac.x += (a) * (w).x; ac.y += (a) * (w).y; ac.z += (a) * (w).z; ac.w += (a) * (w).w; }

__device__ __forceinline__ float tanha(float x) {
    float y;
    asm("tanh.approx.f32 %0, %1;" : "=f"(y) : "f"(x));
    return y;
}

// ---------------- A1: collapsed query/key projections ----------------
__global__ void precompute_qk_kernel(const float* __restrict__ W_query,
                                     const float* __restrict__ b_query,
                                     const float* __restrict__ W_key,
                                     const float* __restrict__ b_key,
                                     const float* __restrict__ W_w) {
    int blk = blockIdx.x, tid = threadIdx.x;
    if (blk == 0) {
        for (int k = tid; k < DD; k += 128) {
            float a = 0.f;
            for (int d = 0; d < DD; d++) a += W_query[d * DD + k] * W_w[d];
            g_vq[k] = a;
        }
        if (tid == 0) {
            float c = 0.f;
            for (int d = 0; d < DD; d++) c += b_query[d] * W_w[d];
            g_cq = c;
        }
    } else {
        for (int k = tid; k < DD; k += 128) {
            float a = 0.f;
            for (int d = 0; d < DD; d++) a += W_key[d * DD + k] * W_w[DD + d];
            g_vk[k] = a;
        }
        if (tid == 0) {
            float c = 0.f;
            for (int d = 0; d < DD; d++) c += b_key[d] * W_w[DD + d];
            g_ck = c;
        }
    }
}

// ---------------- A2: response half of fusion ----------------
__global__ void precompute_resp_kernel(const float* __restrict__ emb_r,
                                       const float* __restrict__ W_fusion,
                                       const float* __restrict__ b_fusion) {
    int r = blockIdx.x, tid = threadIdx.x;
    for (int d = tid; d < DD; d += 128) {
        float a = b_fusion[d];
        for (int k = 0; k < DD; k++)
            a += emb_r[r * DD + k] * W_fusion[d * 2 * DD + DD + k];
        g_resp[r][d] = a;
    }
}

// warp-cooperative 100x100 matvec, approx tanh
__device__ __forceinline__ void mv100(const float* __restrict__ in,
                                      const float* __restrict__ Wg,
                                      const float* __restrict__ bg,
                                      float* out, int tid) {
    int w = tid >> 5, l = tid & 31;
    for (int d = w; d < 100; d += 8) {
        float p = 0.f;
        for (int k = l; k < 100; k += 32) p += in[k] * Wg[d * 100 + k];
        for (int o = 16; o > 0; o >>= 1) p += __shfl_xor_sync(0xffffffffu, p, o);
        if (l == 0) out[d] = tanha(p + bg[d]);
    }
}

// 6x100 matmul, 2x2 reg tiles, 150 threads
__device__ __forceinline__ void mm6(const float* __restrict__ in,
                                    const float* __restrict__ W1T,
                                    const float* __restrict__ b1g,
                                    float* out, int tid) {
    if (tid < 150) {
        int r0 = (tid / 50) * 2, d0 = (tid % 50) * 2;
        float a00 = 0.f, a01 = 0.f, a10 = 0.f, a11 = 0.f;
#pragma unroll 4
        for (int k = 0; k < 100; k++) {
            float2 w = *(const float2*)&W1T[k * 100 + d0];
            float x0 = in[r0 * 100 + k], x1 = in[r0 * 100 + 100 + k];
            a00 += x0 * w.x; a01 += x0 * w.y;
            a10 += x1 * w.x; a11 += x1 * w.y;
        }
        float b0 = b1g[d0], b1 = b1g[d0 + 1];
        out[r0 * 100 + d0] = tanha(a00 + b0);
        out[r0 * 100 + d0 + 1] = tanha(a01 + b1);
        out[r0 * 100 + 100 + d0] = tanha(a10 + b0);
        out[r0 * 100 + 100 + d0 + 1] = tanha(a11 + b1);
    }
}

// ---------------- B: graph aggregation ----------------
__global__ __launch_bounds__(256) void agg_kernel(
    const int* __restrict__ user, const int* __restrict__ question,
    const int* __restrict__ mask,
    const int* __restrict__ q_nb, const int* __restrict__ s_nb,
    const int* __restrict__ u_nb, const int* __restrict__ q_nb2,
    const float* __restrict__ emb_q, const float* __restrict__ emb_q2,
    const float* __restrict__ emb_s, const float* __restrict__ emb_u,
    const float* __restrict__ agg_w, const float* __restrict__ agg_b,
    const float* __restrict__ W_last, const float* __restrict__ b_last) {
    int t = blockIdx.x, b = blockIdx.y, side = blockIdx.z, tid = threadIdx.x;
    int qt = question[b * TT + t];
    float* outg = &g_eagg[side][b][t][0];
    if (mask[b * TT + t] == 0) {
        const float* src = side ? emb_q2 + (size_t)qt * DD : emb_q + (size_t)qt * DD;
        for (int d = tid; d < DD; d += 256) outg[d] = src[d];
        return;
    }
    extern __shared__ float sm[];
    float* W1T = sm;            // 10000
    float* W2T = W1T + 10000;   // 10000
    float* e2s = W2T + 10000;   // 3600
    float* e1  = e2s + 3600;    // 600
    float* e1b = e1 + 600;      // 600
    float* s6  = e1b + 600;     // 600
    float* e0v = s6 + 600;      // 100
    float* e0b = e0v + 100;     // 100
    float* e0c = e0b + 100;     // 100
    float* s1  = e0c + 100;     // 100
    int* sn1 = (int*)(s1 + 100);
    int* sn2 = sn1 + 8;
    int* sn3 = sn2 + 36;

    int n0 = side ? user[b * TT + t] : qt;
    const int* tA = side ? u_nb : q_nb;
    const int* tB = side ? q_nb2 : s_nb;
    const float* eE = side ? emb_u : emb_q;
    const float* eO = side ? emb_q2 : emb_s;
    const float* b0g = agg_b;
    const float* b1g = agg_b + DD;
    const float* b2g = agg_b + 2 * DD;
    const float* W0g = agg_w;

    for (int i = tid; i < 10000; i += 256) {
        int d = i / 100, k = i % 100;
        W1T[k * 100 + d] = agg_w[10000 + i];
        W2T[k * 100 + d] = agg_w[20000 + i];
    }
    if (tid < NBR) sn1[tid] = tA[n0 * NBR + tid];
    for (int d = tid; d < 100; d += 256) e0v[d] = eE[(size_t)n0 * DD + d];
    __syncthreads();
    if (tid < 36) sn2[tid] = tB[sn1[tid / 6] * NBR + tid % 6];
    for (int i = tid; i < 600; i += 256)
        e1[i] = eO[(size_t)sn1[i / 100] * DD + i % 100];
    __syncthreads();
    if (tid < 216) sn3[tid] = tA[sn2[tid / 6] * NBR + tid % 6];
    for (int i = tid; i < 3600; i += 256)
        e2s[i] = eE[(size_t)sn2[i / 100] * DD + i % 100];
    __syncthreads();
    for (int i = tid; i < 600; i += 256) {
        int r = i / 100, d = i % 100;
        float s = 0.f;
        for (int r2 = 0; r2 < 6; r2++) s += e2s[(r * 6 + r2) * 100 + d];
        s6[i] = s * (1.f / 6.f) + e1[i];
    }
    if (tid < 100) {
        float s = 0.f;
        for (int r = 0; r < 6; r++) s += e1[r * 100 + tid];
        s1[tid] = s * (1.f / 6.f) + e0v[tid];
    }
    __syncthreads();
    mv100(s1, W0g, b0g, e0b, tid);  // i=0 j=0
    for (int i = tid; i < 3600; i += 256) {
        int g = i / 100, d = i % 100;
        float s = 0.f;
#pragma unroll
        for (int r = 0; r < 6; r++) s += eO[(size_t)sn3[g * 6 + r] * DD + d];
        e2s[i] += s * (1.f / 6.f);
    }
    __syncthreads();
    // i=0 j=2 : 36x100, 4x4 reg tiles, in-place
    float4 ac0, ac1, ac2, ac3;
    int r0 = 0, d0 = 0;
    if (tid < 225) {
        r0 = (tid / 25) * 4; d0 = (tid % 25) * 4;
        ac0 = make_float4(0, 0, 0, 0); ac1 = ac0; ac2 = ac0; ac3 = ac0;
#pragma unroll 2
        for (int k = 0; k < 100; k++) {
            float4 w = *(const float4*)&W2T[k * 100 + d0];
            float x0 = e2s[r0 * 100 + k];
            float x1 = e2s[r0 * 100 + 100 + k];
            float x2 = e2s[r0 * 100 + 200 + k];
            float x3 = e2s[r0 * 100 + 300 + k];
            FMA4(ac0, x0, w); FMA4(ac1, x1, w); FMA4(ac2, x2, w); FMA4(ac3, x3, w);
        }
    }
    __syncthreads();
    if (tid < 225) {
        float bb0 = b2g[d0], bb1 = b2g[d0 + 1], bb2 = b2g[d0 + 2], bb3 = b2g[d0 + 3];
        float* o0 = e2s + r0 * 100 + d0;
        o0[0] = tanha(ac0.x + bb0); o0[1] = tanha(ac0.y + bb1); o0[2] = tanha(ac0.z + bb2); o0[3] = tanha(ac0.w + bb3);
        o0[100] = tanha(ac1.x + bb0); o0[101] = tanha(ac1.y + bb1); o0[102] = tanha(ac1.z + bb2); o0[103] = tanha(ac1.w + bb3);
        o0[200] = tanha(ac2.x + bb0); o0[201] = tanha(ac2.y + bb1); o0[202] = tanha(ac2.z + bb2); o0[203] = tanha(ac2.w + bb3);
        o0[300] = tanha(ac3.x + bb0); o0[301] = tanha(ac3.y + bb1); o0[302] = tanha(ac3.z + bb2); o0[303] = tanha(ac3.w + bb3);
    }
    mm6(s6, W1T, b1g, e1b, tid);    // i=0 j=1
    __syncthreads();
    for (int i = tid; i < 600; i += 256) {
        int r = i / 100, d = i % 100;
        float s = 0.f;
        for (int r2 = 0; r2 < 6; r2++) s += e2s[(r * 6 + r2) * 100 + d];
        s6[i] = s * (1.f / 6.f) + e1b[i];
    }
    if (tid < 100) {
        float s = 0.f;
        for (int r = 0; r < 6; r++) s += e1b[r * 100 + tid];
        s1[tid] = s * (1.f / 6.f) + e0b[tid];
    }
    __syncthreads();
    mv100(s1, W0g, b0g, e0c, tid);  // i=1 j=0
    mm6(s6, W1T, b1g, e1, tid);     // i=1 j=1
    __syncthreads();
    if (tid < 100) {
        float s = 0.f;
        for (int r = 0; r < 6; r++) s += e1[r * 100 + tid];
        s1[tid] = s * (1.f / 6.f) + e0c[tid];
    }
    __syncthreads();
    mv100(s1, W0g, b0g, e0v, tid);  // i=2 j=0
    __syncthreads();
    mv100(e0v, W_last, b_last, outg, tid);  // final
}

// ---------------- C: qs_concat / ql / static top-k ----------------
__global__ __launch_bounds__(128) void prep_kernel(
    const int* __restrict__ question, const int* __restrict__ qs_index,
    const float* __restrict__ emb_q, const float* __restrict__ emb_s) {
    int t = blockIdx.x, b = blockIdx.y, tid = threadIdx.x;
    __shared__ float qsm[500];
    __shared__ float sc[TS];
    int qn = question[b * TT + t + 1];
    for (int i = tid; i < 500; i += 128) {
        int q = i / 100, d = i % 100;
        float v = (q == 0) ? emb_q[(size_t)qn * DD + d]
                           : emb_s[(size_t)qs_index[qn * SPQ + q - 1] * DD + d];
        qsm[i] = v;
        g_qsc[b][t][q][d] = v;
    }
    __syncthreads();
    if (tid < 5) {
        float a = g_cq;
        for (int d = 0; d < 100; d++) a += qsm[tid * 100 + d] * g_vq[d];
        g_ql[b][t][tid] = a;
    }
    for (int i = tid; i < t; i += 128) {
        const float* er = emb_q + (size_t)question[b * TT + i] * DD;
        float a = 0.f;
#pragma unroll 4
        for (int d = 0; d < 100; d++) a += er[d] * qsm[d];
        sc[i] = a;
    }
    __syncthreads();
    if (tid == 0) {
        unsigned long long used = 0ULL;
        for (int s = 0; s < RK; s++) {
            float best = -1e38f; int bi = -1;
            for (int i = 0; i < t; i++)
                if (!((used >> i) & 1ULL) && sc[i] > best) { best = sc[i]; bi = i; }
            if (bi >= 0) { g_idx[b][t][s] = bi; g_sval[b][t][s] = 1; used |= 1ULL << bi; }
            else         { g_idx[b][t][s] = 0;  g_sval[b][t][s] = 0; }
        }
    }
}

// ---------------- D1: fusion e_t, grid (13 t-chunks, 32 b) ----------------
__global__ __launch_bounds__(256) void fusion_et_kernel(
    const int* __restrict__ response, const float* __restrict__ w1p,
    const float* __restrict__ w2p, const float* __restrict__ W_fusion) {
    int tc = blockIdx.x, b = blockIdx.y, tid = threadIdx.x;
    int t0 = tc * 4;
    extern __shared__ float sm[];
    float* WT = sm;          // 10000
    float* eh = WT + 10000;  // 400
    for (int i = tid; i < 10000; i += 256) {
        int d = i / 100, k = i % 100;
        WT[k * 100 + d] = W_fusion[d * 200 + k];
    }
    float w1 = *w1p, w2 = *w2p;
    for (int i = tid; i < 400; i += 256) {
        int t = t0 + i / 100, d = i % 100;
        eh[i] = (t < TS) ? w1 * g_eagg[0][b][t][d] + w2 * g_eagg[1][b][t][d] : 0.f;
    }
    __syncthreads();
    if (tid < 100) {
        int tt = tid / 25, d0 = (tid % 25) * 4;
        int t = t0 + tt;
        if (t < TS) {
            float4 ac = make_float4(0, 0, 0, 0);
#pragma unroll 4
            for (int k = 0; k < 100; k++) {
                float4 w = *(const float4*)&WT[k * 100 + d0];
                FMA4(ac, eh[tt * 100 + k], w);
            }
            int r = response[b * TT + t];
            g_et[b][t][d0]     = fmaxf(ac.x + g_resp[r][d0], 0.f);
            g_et[b][t][d0 + 1] = fmaxf(ac.y + g_resp[r][d0 + 1], 0.f);
            g_et[b][t][d0 + 2] = fmaxf(ac.z + g_resp[r][d0 + 2], 0.f);
            g_et[b][t][d0 + 3] = fmaxf(ac.w + g_resp[r][d0 + 3], 0.f);
        }
    }
}

// ---------------- D2: input gates, grid (4 j, 4 tq, 32 b) ----------------
__global__ __launch_bounds__(256) void gates_kernel(
    const float* __restrict__ W_ih, const float* __restrict__ b_ih,
    const float* __restrict__ b_hh) {
    int jc = blockIdx.x, tq = blockIdx.y, b = blockIdx.z, tid = threadIdx.x;
    int t0 = tq * 13;
    int nt = min(13, TS - t0);
    extern __shared__ float sm[];
    float* WT = sm;          // 10000
    float* et = WT + 10000;  // 1300
    for (int i = tid; i < 10000; i += 256) {
        int jj = i / 100, k = i % 100;
        WT[k * 100 + jj] = W_ih[(jc * 100 + jj) * 100 + k];
    }
    for (int i = tid; i < nt * 100; i += 256)
        et[i] = g_et[b][t0 + i / 100][i % 100];
    __syncthreads();
    for (int u = tid; u < nt * 25; u += 256) {
        int tt = u / 25, j0 = (u % 25) * 4;
        float4 ac = make_float4(0, 0, 0, 0);
#pragma unroll 4
        for (int k = 0; k < 100; k++) {
            float4 w = *(const float4*)&WT[k * 100 + j0];
            FMA4(ac, et[tt * 100 + k], w);
        }
        int jg = jc * 100 + j0;
        int t = t0 + tt;
        g_gates[b][t][jg]     = ac.x + b_ih[jg] + b_hh[jg];
        g_gates[b][t][jg + 1] = ac.y + b_ih[jg + 1] + b_hh[jg + 1];
        g_gates[b][t][jg + 2] = ac.z + b_ih[jg + 2] + b_hh[jg + 2];
        g_gates[b][t][jg + 3] = ac.w + b_ih[jg + 3] + b_hh[jg + 3];
    }
}

// ---------------- E: LSTM scan, skip masked steps ----------------
__global__ __launch_bounds__(128) void scan_kernel(
    const int* __restrict__ mask, const float* __restrict__ W_hh,
    float* __restrict__ out) {
    int b = blockIdx.x, tid = threadIdx.x;
    extern __shared__ float sm[];
    float* WT = sm;           // 100*404
    float* h  = WT + 40400;
    float* c  = h + 100;
    float* gs = c + 100;
    for (int i = tid; i < 40000; i += 128) {
        int j = i / 100, d = i % 100;
        WT[d * 404 + j] = W_hh[i];
    }
    for (int i = tid; i < 100; i += 128) { h[i] = 0.f; c[i] = 0.f; }
    if (tid == 0) out[b * TT] = 0.5f;
    __syncthreads();
    for (int t = 0; t < TS; t++) {
        if (mask[b * TT + t]) {
            if (tid < 100) {
                float4 gin = *(const float4*)&g_gates[b][t][tid * 4];
                float4 ac = make_float4(0, 0, 0, 0);
#pragma unroll 4
                for (int d = 0; d < 100; d++) {
                    float hb = h[d];
                    float4 w = *(const float4*)&WT[d * 404 + tid * 4];
                    FMA4(ac, hb, w);
                }
                gs[tid * 4]     = ac.x + gin.x;
                gs[tid * 4 + 1] = ac.y + gin.y;
                gs[tid * 4 + 2] = ac.z + gin.z;
                gs[tid * 4 + 3] = ac.w + gin.w;
            }
            __syncthreads();
            if (tid < 100) {
                float gi = gs[tid], gf = gs[100 + tid], gg = gs[200 + tid], go = gs[300 + tid];
                float si = 1.f / (1.f + expf(-gi));
                float sf = 1.f / (1.f + expf(-gf));
                float so = 1.f / (1.f + expf(-go));
                float c2 = sf * c[tid] + si * tanhf(gg);
                float h2 = so * tanhf(c2);
                h[tid] = h2; c[tid] = c2;
                g_h[b][t][tid] = h2;
            }
            __syncthreads();
        } else {
            if (tid < 100) g_h[b][t][tid] = h[tid];
        }
    }
}

// ---------------- F: attention readout ----------------
__global__ __launch_bounds__(128) void attn_kernel(const float* __restrict__ b_w,
                                                   float* __restrict__ out) {
    int t = blockIdx.x, b = blockIdx.y, tid = threadIdx.x;
    __shared__ float st[1100], qsm[500], vks[100], lbuf[64], gbuf[64], klb[16], red[2], sql[5];
    __shared__ int sidx[10], ssv[10];
    if (tid < 10) { sidx[tid] = g_idx[b][t][tid]; ssv[tid] = g_sval[b][t][tid]; }
    if (tid >= 16 && tid < 21) sql[tid - 16] = g_ql[b][t][tid - 16];
    __syncthreads();
    for (int i = tid; i < 1100; i += 128) {
        int s = i / 100, d = i % 100;
        int row = (s == 0) ? t : sidx[s - 1];
        st[i] = g_h[b][row][d];
    }
    for (int i = tid; i < 500; i += 128) qsm[i] = (&g_qsc[b][t][0][0])[i];
    for (int d = tid; d < 100; d += 128) vks[d] = g_vk[d];
    __syncthreads();
    float ckb = g_ck + b_w[0];
    if (tid < 55) {
        int q = tid / 11, s = tid % 11;
        bool v = (s == 0) || ssv[s - 1];
        float a = 0.f;
        if (v) {
            const float* qr = qsm + q * 100;
            const float* sr = st + s * 100;
#pragma unroll 4
            for (int d = 0; d < 100; d++) a += qr[d] * sr[d];
        }
        gbuf[tid] = a;
    } else if (tid < 66) {
        int s = tid - 55;
        bool v = (s == 0) || ssv[s - 1];
        float a = -1e30f;
        if (v) {
            a = ckb;
            const float* sr = st + s * 100;
#pragma unroll 4
            for (int d = 0; d < 100; d++) a += sr[d] * vks[d];
        }
        klb[s] = a;
    }
    __syncthreads();
    if (tid < 64) lbuf[tid] = (tid < 55) ? sql[tid / 11] + klb[tid % 11] : -1e30f;
    __syncthreads();
    if (tid < 32) {
        float mx = fmaxf(lbuf[tid], lbuf[tid + 32]);
        for (int o = 16; o > 0; o >>= 1)
            mx = fmaxf(mx, __shfl_xor_sync(0xffffffffu, mx, o));
        if (tid == 0) red[0] = mx;
    }
    __syncthreads();
    if (tid < 64) {
        float e = (tid < 55) ? expf(lbuf[tid] - red[0]) : 0.f;
        lbuf[tid] = e;
        gbuf[tid] = (tid < 55) ? gbuf[tid] * e : 0.f;
    }
    __syncthreads();
    if (tid < 32) {
        float se = lbuf[tid] + lbuf[tid + 32];
        float sp = gbuf[tid] + gbuf[tid + 32];
        for (int o = 16; o > 0; o >>= 1) {
            se += __shfl_xor_sync(0xffffffffu, se, o);
            sp += __shfl_xor_sync(0xffffffffu, sp, o);
        }
        if (tid == 0) out[b * TT + t + 1] = 1.f / (1.f + expf(-sp / se));
    }
}

// ---------------- launch ----------------
extern "C" void kernel_launch(void* const* d_in, const int* in_sizes, int n_in,
                              void* d_out, int out_size) {
    const int* user      = (const int*)d_in[0];
    const int* question  = (const int*)d_in[1];
    const int* response  = (const int*)d_in[2];
    const int* mask      = (const int*)d_in[3];
    const int* q_nb      = (const int*)d_in[4];
    const int* s_nb      = (const int*)d_in[5];
    const int* u_nb      = (const int*)d_in[6];
    const int* q_nb2     = (const int*)d_in[7];
    const int* qs_index  = (const int*)d_in[8];
    const float* emb_q   = (const float*)d_in[9];
    const float* emb_q2  = (const float*)d_in[10];
    const float* emb_s   = (const float*)d_in[11];
    const float* emb_u   = (const float*)d_in[12];
    const float* emb_r   = (const float*)d_in[13];
    const float* w1      = (const float*)d_in[14];
    const float* w2      = (const float*)d_in[15];
    const float* W_ih    = (const float*)d_in[16];
    const float* W_hh    = (const float*)d_in[17];
    const float* b_ih    = (const float*)d_in[18];
    const float* b_hh    = (const float*)d_in[19];
    const float* agg_w   = (const float*)d_in[20];
    const float* agg_b   = (const float*)d_in[21];
    const float* W_al    = (const float*)d_in[22];
    const float* b_al    = (const float*)d_in[23];
    const float* W_query = (const float*)d_in[24];
    const float* b_query = (const float*)d_in[25];
    const float* W_key   = (const float*)d_in[26];
    const float* b_key   = (const float*)d_in[27];
    const float* W_w     = (const float*)d_in[28];
    const float* b_w     = (const float*)d_in[29];
    const float* W_fus   = (const float*)d_in[30];
    const float* b_fus   = (const float*)d_in[31];
    float* out = (float*)d_out;

    const size_t agg_sm  = 104448;
    const size_t fus_sm  = 10400 * 4;
    const size_t gat_sm  = 11300 * 4;
    const size_t scan_sm = 41000 * 4;
    cudaFuncSetAttribute(agg_kernel, cudaFuncAttributeMaxDynamicSharedMemorySize, (int)agg_sm);
    cudaFuncSetAttribute(fusion_et_kernel, cudaFuncAttributeMaxDynamicSharedMemorySize, (int)fus_sm);
    cudaFuncSetAttribute(gates_kernel, cudaFuncAttributeMaxDynamicSharedMemorySize, (int)gat_sm);
    cudaFuncSetAttribute(scan_kernel, cudaFuncAttributeMaxDynamicSharedMemorySize, (int)scan_sm);

    // order chosen so agg_kernel is the 4th launch (gets profiled by ncu -s 5)
    precompute_qk_kernel<<<2, 128>>>(W_query, b_query, W_key, b_key, W_w);
    precompute_resp_kernel<<<2, 128>>>(emb_r, W_fus, b_fus);
    prep_kernel<<<dim3(TS, TB), 128>>>(question, qs_index, emb_q, emb_s);
    agg_kernel<<<dim3(TS, TB, 2), 256, agg_sm>>>(user, question, mask, q_nb, s_nb,
                                                 u_nb, q_nb2, emb_q, emb_q2, emb_s,
                                                 emb_u, agg_w, agg_b, W_al, b_al);
    fusion_et_kernel<<<dim3(13, TB), 256, fus_sm>>>(response, w1, w2, W_fus);
    gates_kernel<<<dim3(4, 4, TB), 256, gat_sm>>>(W_ih, b_ih, b_hh);
    scan_kernel<<<TB, 128, scan_sm>>>(mask, W_hh, out);
    attn_kernel<<<dim3(TS, TB), 128>>>(b_w, out);
}

// round 7
// speedup vs baseline: 2.2203x; 1.4437x over previous
#include <cuda_runtime.h>

#define TB 32
#define TT 50
#define TS 49
#define DD 100
#define NBR 6
#define SPQ 4
#define RK 10

// ---------------- device scratch (16B-aligned; scalars last) ----------------
__device__ __align__(16) float g_eagg[2][TB][TS][DD];
__device__ __align__(16) float g_et[TB][TS][DD];
__device__ __align__(16) float g_gates[TB][TS][4 * DD];
__device__ __align__(16) float g_qsc[TB][TS][5][DD];
__device__ __align__(16) float g_ql[TB][TS][5];
__device__ __align__(16) float g_h[TB][TS][DD];
__device__ __align__(16) int   g_idx[TB][TS][RK];
__device__ __align__(16) int   g_sval[TB][TS][RK];
__device__ __align__(16) float g_vq[DD], g_vk[DD];
__device__ __align__(16) float g_resp[2][DD];
__device__ __align__(16) float g_w1t[10000];   // W1^T : g_w1t[k*100+d] = agg_w[1][d][k]
__device__ __align__(16) float g_w2t[10000];   // W2^T
__device__ float g_cq, g_ck;

#define FMA4(ac, a, w) { ac.x += (a) * (w).x; ac.y += (a) * (w).y; ac.z += (a) * (w).z; ac.w += (a) * (w).w; }

__device__ __forceinline__ float tanha(float x) {
    float y;
    asm("tanh.approx.f32 %0, %1;" : "=f"(y) : "f"(x));
    return y;
}

// ---------------- A1: collapsed query/key projections ----------------
__global__ void precompute_qk_kernel(const float* __restrict__ W_query,
                                     const float* __restrict__ b_query,
                                     const float* __restrict__ W_key,
                                     const float* __restrict__ b_key,
                                     const float* __restrict__ W_w) {
    int blk = blockIdx.x, tid = threadIdx.x;
    if (blk == 0) {
        for (int k = tid; k < DD; k += 128) {
            float a = 0.f;
            for (int d = 0; d < DD; d++) a += W_query[d * DD + k] * W_w[d];
            g_vq[k] = a;
        }
        if (tid == 0) {
            float c = 0.f;
            for (int d = 0; d < DD; d++) c += b_query[d] * W_w[d];
            g_cq = c;
        }
    } else {
        for (int k = tid; k < DD; k += 128) {
            float a = 0.f;
            for (int d = 0; d < DD; d++) a += W_key[d * DD + k] * W_w[DD + d];
            g_vk[k] = a;
        }
        if (tid == 0) {
            float c = 0.f;
            for (int d = 0; d < DD; d++) c += b_key[d] * W_w[DD + d];
            g_ck = c;
        }
    }
}

// ---------------- A2: response half of fusion ----------------
__global__ void precompute_resp_kernel(const float* __restrict__ emb_r,
                                       const float* __restrict__ W_fusion,
                                       const float* __restrict__ b_fusion) {
    int r = blockIdx.x, tid = threadIdx.x;
    for (int d = tid; d < DD; d += 128) {
        float a = b_fusion[d];
        for (int k = 0; k < DD; k++)
            a += emb_r[r * DD + k] * W_fusion[d * 2 * DD + DD + k];
        g_resp[r][d] = a;
    }
}

// ---------------- A3: transpose W1, W2 into global ----------------
__global__ void transpose_w_kernel(const float* __restrict__ agg_w) {
    int blk = blockIdx.x, tid = threadIdx.x;
    const float* src = agg_w + (blk + 1) * 10000;
    float* dst = blk ? g_w2t : g_w1t;
    for (int i = tid; i < 10000; i += 256) {
        int d = i / 100, k = i % 100;
        dst[k * 100 + d] = src[i];
    }
}

// warp-cooperative 100x100 matvec (weights from global, coalesced rows)
__device__ __forceinline__ void mv100(const float* __restrict__ in,
                                      const float* __restrict__ Wg,
                                      const float* __restrict__ bg,
                                      float* out, int tid) {
    int w = tid >> 5, l = tid & 31;
    for (int d = w; d < 100; d += 8) {
        float p = 0.f;
        for (int k = l; k < 100; k += 32) p += in[k] * Wg[d * 100 + k];
        for (int o = 16; o > 0; o >>= 1) p += __shfl_xor_sync(0xffffffffu, p, o);
        if (l == 0) out[d] = tanha(p + bg[d]);
    }
}

// 6x100 matmul, 2x2 reg tiles, 150 threads, W^T from global
__device__ __forceinline__ void mm6(const float* __restrict__ in,
                                    const float* __restrict__ W1T,
                                    const float* __restrict__ b1g,
                                    float* out, int tid) {
    if (tid < 150) {
        int r0 = (tid / 50) * 2, d0 = (tid % 50) * 2;
        float a00 = 0.f, a01 = 0.f, a10 = 0.f, a11 = 0.f;
#pragma unroll 4
        for (int k = 0; k < 100; k++) {
            float2 w = *(const float2*)&W1T[k * 100 + d0];
            float x0 = in[r0 * 100 + k], x1 = in[r0 * 100 + 100 + k];
            a00 += x0 * w.x; a01 += x0 * w.y;
            a10 += x1 * w.x; a11 += x1 * w.y;
        }
        float b0 = b1g[d0], b1 = b1g[d0 + 1];
        out[r0 * 100 + d0] = tanha(a00 + b0);
        out[r0 * 100 + d0 + 1] = tanha(a01 + b1);
        out[r0 * 100 + 100 + d0] = tanha(a10 + b0);
        out[r0 * 100 + 100 + d0 + 1] = tanha(a11 + b1);
    }
}

// ---------------- B: graph aggregation (24 KB smem -> 4 CTAs/SM) ----------------
__global__ __launch_bounds__(256) void agg_kernel(
    const int* __restrict__ user, const int* __restrict__ question,
    const int* __restrict__ mask,
    const int* __restrict__ q_nb, const int* __restrict__ s_nb,
    const int* __restrict__ u_nb, const int* __restrict__ q_nb2,
    const float* __restrict__ emb_q, const float* __restrict__ emb_q2,
    const float* __restrict__ emb_s, const float* __restrict__ emb_u,
    const float* __restrict__ agg_w, const float* __restrict__ agg_b,
    const float* __restrict__ W_last, const float* __restrict__ b_last) {
    int t = blockIdx.x, b = blockIdx.y, side = blockIdx.z, tid = threadIdx.x;
    int qt = question[b * TT + t];
    float* outg = &g_eagg[side][b][t][0];
    if (mask[b * TT + t] == 0) {
        const float* src = side ? emb_q2 + (size_t)qt * DD : emb_q + (size_t)qt * DD;
        for (int d = tid; d < DD; d += 256) outg[d] = src[d];
        return;
    }
    extern __shared__ float sm[];
    float* e2s = sm;            // 3600
    float* e1  = e2s + 3600;    // 600
    float* e1b = e1 + 600;      // 600
    float* s6  = e1b + 600;     // 600
    float* e0v = s6 + 600;      // 100
    float* e0b = e0v + 100;     // 100
    float* e0c = e0b + 100;     // 100
    float* s1  = e0c + 100;     // 100  -> 5800 floats total
    int* sn1 = (int*)(s1 + 100);  // 8
    int* sn2 = sn1 + 8;           // 36
    int* sn3 = sn2 + 36;          // 216 -> 260 ints total

    int n0 = side ? user[b * TT + t] : qt;
    const int* tA = side ? u_nb : q_nb;
    const int* tB = side ? q_nb2 : s_nb;
    const float* eE = side ? emb_u : emb_q;
    const float* eO = side ? emb_q2 : emb_s;
    const float* b0g = agg_b;
    const float* b1g = agg_b + DD;
    const float* b2g = agg_b + 2 * DD;
    const float* W0g = agg_w;

    if (tid < NBR) sn1[tid] = tA[n0 * NBR + tid];
    for (int d = tid; d < 100; d += 256) e0v[d] = eE[(size_t)n0 * DD + d];
    __syncthreads();
    if (tid < 36) sn2[tid] = tB[sn1[tid / 6] * NBR + tid % 6];
    for (int i = tid; i < 600; i += 256)
        e1[i] = eO[(size_t)sn1[i / 100] * DD + i % 100];
    __syncthreads();
    if (tid < 216) sn3[tid] = tA[sn2[tid / 6] * NBR + tid % 6];
    for (int i = tid; i < 3600; i += 256)
        e2s[i] = eE[(size_t)sn2[i / 100] * DD + i % 100];
    __syncthreads();
    // originals: s6 = groupmean(e2)+e1, s1 = mean(e1)+e0
    for (int i = tid; i < 600; i += 256) {
        int r = i / 100, d = i % 100;
        float s = 0.f;
        for (int r2 = 0; r2 < 6; r2++) s += e2s[(r * 6 + r2) * 100 + d];
        s6[i] = s * (1.f / 6.f) + e1[i];
    }
    if (tid < 100) {
        float s = 0.f;
        for (int r = 0; r < 6; r++) s += e1[r * 100 + tid];
        s1[tid] = s * (1.f / 6.f) + e0v[tid];
    }
    __syncthreads();
    mv100(s1, W0g, b0g, e0b, tid);  // i=0 j=0
    // e2s += hop3 means (gathered)
    for (int i = tid; i < 3600; i += 256) {
        int g = i / 100, d = i % 100;
        float s = 0.f;
#pragma unroll
        for (int r = 0; r < 6; r++) s += eO[(size_t)sn3[g * 6 + r] * DD + d];
        e2s[i] += s * (1.f / 6.f);
    }
    __syncthreads();
    // i=0 j=2 : 36x100 @ W2^T (global), 4x4 reg tiles, in-place
    float4 ac0, ac1, ac2, ac3;
    int r0 = 0, d0 = 0;
    if (tid < 225) {
        r0 = (tid / 25) * 4; d0 = (tid % 25) * 4;
        ac0 = make_float4(0, 0, 0, 0); ac1 = ac0; ac2 = ac0; ac3 = ac0;
#pragma unroll 2
        for (int k = 0; k < 100; k++) {
            float4 w = *(const float4*)&g_w2t[k * 100 + d0];
            float x0 = e2s[r0 * 100 + k];
            float x1 = e2s[r0 * 100 + 100 + k];
            float x2 = e2s[r0 * 100 + 200 + k];
            float x3 = e2s[r0 * 100 + 300 + k];
            FMA4(ac0, x0, w); FMA4(ac1, x1, w); FMA4(ac2, x2, w); FMA4(ac3, x3, w);
        }
    }
    __syncthreads();
    if (tid < 225) {
        float bb0 = b2g[d0], bb1 = b2g[d0 + 1], bb2 = b2g[d0 + 2], bb3 = b2g[d0 + 3];
        float* o0 = e2s + r0 * 100 + d0;
        o0[0] = tanha(ac0.x + bb0); o0[1] = tanha(ac0.y + bb1); o0[2] = tanha(ac0.z + bb2); o0[3] = tanha(ac0.w + bb3);
        o0[100] = tanha(ac1.x + bb0); o0[101] = tanha(ac1.y + bb1); o0[102] = tanha(ac1.z + bb2); o0[103] = tanha(ac1.w + bb3);
        o0[200] = tanha(ac2.x + bb0); o0[201] = tanha(ac2.y + bb1); o0[202] = tanha(ac2.z + bb2); o0[203] = tanha(ac2.w + bb3);
        o0[300] = tanha(ac3.x + bb0); o0[301] = tanha(ac3.y + bb1); o0[302] = tanha(ac3.z + bb2); o0[303] = tanha(ac3.w + bb3);
    }
    mm6(s6, g_w1t, b1g, e1b, tid);  // i=0 j=1 (reads stable s6)
    __syncthreads();
    for (int i = tid; i < 600; i += 256) {
        int r = i / 100, d = i % 100;
        float s = 0.f;
        for (int r2 = 0; r2 < 6; r2++) s += e2s[(r * 6 + r2) * 100 + d];
        s6[i] = s * (1.f / 6.f) + e1b[i];
    }
    if (tid < 100) {
        float s = 0.f;
        for (int r = 0; r < 6; r++) s += e1b[r * 100 + tid];
        s1[tid] = s * (1.f / 6.f) + e0b[tid];
    }
    __syncthreads();
    mv100(s1, W0g, b0g, e0c, tid);  // i=1 j=0
    mm6(s6, g_w1t, b1g, e1, tid);   // i=1 j=1
    __syncthreads();
    if (tid < 100) {
        float s = 0.f;
        for (int r = 0; r < 6; r++) s += e1[r * 100 + tid];
        s1[tid] = s * (1.f / 6.f) + e0c[tid];
    }
    __syncthreads();
    mv100(s1, W0g, b0g, e0v, tid);  // i=2 j=0
    __syncthreads();
    mv100(e0v, W_last, b_last, outg, tid);  // final
}

// ---------------- C: qs_concat / ql / static top-k ----------------
__global__ __launch_bounds__(128) void prep_kernel(
    const int* __restrict__ question, const int* __restrict__ qs_index,
    const float* __restrict__ emb_q, const float* __restrict__ emb_s) {
    int t = blockIdx.x, b = blockIdx.y, tid = threadIdx.x;
    __shared__ float qsm[500];
    __shared__ float sc[TS];
    int qn = question[b * TT + t + 1];
    for (int i = tid; i < 500; i += 128) {
        int q = i / 100, d = i % 100;
        float v = (q == 0) ? emb_q[(size_t)qn * DD + d]
                           : emb_s[(size_t)qs_index[qn * SPQ + q - 1] * DD + d];
        qsm[i] = v;
        g_qsc[b][t][q][d] = v;
    }
    __syncthreads();
    if (tid < 5) {
        float a = g_cq;
        for (int d = 0; d < 100; d++) a += qsm[tid * 100 + d] * g_vq[d];
        g_ql[b][t][tid] = a;
    }
    for (int i = tid; i < t; i += 128) {
        const float* er = emb_q + (size_t)question[b * TT + i] * DD;
        float a = 0.f;
#pragma unroll 4
        for (int d = 0; d < 100; d++) a += er[d] * qsm[d];
        sc[i] = a;
    }
    __syncthreads();
    if (tid == 0) {
        unsigned long long used = 0ULL;
        for (int s = 0; s < RK; s++) {
            float best = -1e38f; int bi = -1;
            for (int i = 0; i < t; i++)
                if (!((used >> i) & 1ULL) && sc[i] > best) { best = sc[i]; bi = i; }
            if (bi >= 0) { g_idx[b][t][s] = bi; g_sval[b][t][s] = 1; used |= 1ULL << bi; }
            else         { g_idx[b][t][s] = 0;  g_sval[b][t][s] = 0; }
        }
    }
}

// ---------------- D1: fusion e_t ----------------
__global__ __launch_bounds__(256) void fusion_et_kernel(
    const int* __restrict__ response, const float* __restrict__ w1p,
    const float* __restrict__ w2p, const float* __restrict__ W_fusion) {
    int tc = blockIdx.x, b = blockIdx.y, tid = threadIdx.x;
    int t0 = tc * 4;
    extern __shared__ float sm[];
    float* WT = sm;          // 10000
    float* eh = WT + 10000;  // 400
    for (int i = tid; i < 10000; i += 256) {
        int d = i / 100, k = i % 100;
        WT[k * 100 + d] = W_fusion[d * 200 + k];
    }
    float w1 = *w1p, w2 = *w2p;
    for (int i = tid; i < 400; i += 256) {
        int t = t0 + i / 100, d = i % 100;
        eh[i] = (t < TS) ? w1 * g_eagg[0][b][t][d] + w2 * g_eagg[1][b][t][d] : 0.f;
    }
    __syncthreads();
    if (tid < 100) {
        int tt = tid / 25, d0 = (tid % 25) * 4;
        int t = t0 + tt;
        if (t < TS) {
            float4 ac = make_float4(0, 0, 0, 0);
#pragma unroll 4
            for (int k = 0; k < 100; k++) {
                float4 w = *(const float4*)&WT[k * 100 + d0];
                FMA4(ac, eh[tt * 100 + k], w);
            }
            int r = response[b * TT + t];
            g_et[b][t][d0]     = fmaxf(ac.x + g_resp[r][d0], 0.f);
            g_et[b][t][d0 + 1] = fmaxf(ac.y + g_resp[r][d0 + 1], 0.f);
            g_et[b][t][d0 + 2] = fmaxf(ac.z + g_resp[r][d0 + 2], 0.f);
            g_et[b][t][d0 + 3] = fmaxf(ac.w + g_resp[r][d0 + 3], 0.f);
        }
    }
}

// ---------------- D2: input gates ----------------
__global__ __launch_bounds__(256) void gates_kernel(
    const float* __restrict__ W_ih, const float* __restrict__ b_ih,
    const float* __restrict__ b_hh) {
    int jc = blockIdx.x, tq = blockIdx.y, b = blockIdx.z, tid = threadIdx.x;
    int t0 = tq * 13;
    int nt = min(13, TS - t0);
    extern __shared__ float sm[];
    float* WT = sm;          // 10000
    float* et = WT + 10000;  // 1300
    for (int i = tid; i < 10000; i += 256) {
        int jj = i / 100, k = i % 100;
        WT[k * 100 + jj] = W_ih[(jc * 100 + jj) * 100 + k];
    }
    for (int i = tid; i < nt * 100; i += 256)
        et[i] = g_et[b][t0 + i / 100][i % 100];
    __syncthreads();
    for (int u = tid; u < nt * 25; u += 256) {
        int tt = u / 25, j0 = (u % 25) * 4;
        float4 ac = make_float4(0, 0, 0, 0);
#pragma unroll 4
        for (int k = 0; k < 100; k++) {
            float4 w = *(const float4*)&WT[k * 100 + j0];
            FMA4(ac, et[tt * 100 + k], w);
        }
        int jg = jc * 100 + j0;
        int t = t0 + tt;
        g_gates[b][t][jg]     = ac.x + b_ih[jg] + b_hh[jg];
        g_gates[b][t][jg + 1] = ac.y + b_ih[jg + 1] + b_hh[jg + 1];
        g_gates[b][t][jg + 2] = ac.z + b_ih[jg + 2] + b_hh[jg + 2];
        g_gates[b][t][jg + 3] = ac.w + b_ih[jg + 3] + b_hh[jg + 3];
    }
}

// ---------------- E: LSTM scan, skip masked steps, 200x2 matvec ----------------
__global__ __launch_bounds__(256) void scan_kernel(
    const int* __restrict__ mask, const float* __restrict__ W_hh,
    float* __restrict__ out) {
    int b = blockIdx.x, tid = threadIdx.x;
    extern __shared__ float sm[];
    float* WT = sm;           // 100*402, WT[d*402+j]
    float* h  = WT + 40200;
    float* c  = h + 100;
    float* gs = c + 100;
    for (int i = tid; i < 40000; i += 256) {
        int j = i / 100, d = i % 100;
        WT[d * 402 + j] = W_hh[i];
    }
    for (int i = tid; i < 100; i += 256) { h[i] = 0.f; c[i] = 0.f; }
    if (tid == 0) out[b * TT] = 0.5f;
    __syncthreads();
    for (int t = 0; t < TS; t++) {
        if (mask[b * TT + t]) {
            if (tid < 200) {
                int j0 = tid * 2;
                float2 gin = *(const float2*)&g_gates[b][t][j0];
                float ax = 0.f, ay = 0.f;
#pragma unroll 4
                for (int d = 0; d < 100; d++) {
                    float hb = h[d];
                    float2 w = *(const float2*)&WT[d * 402 + j0];
                    ax += hb * w.x; ay += hb * w.y;
                }
                gs[j0] = ax + gin.x;
                gs[j0 + 1] = ay + gin.y;
            }
            __syncthreads();
            if (tid < 100) {
                float gi = gs[tid], gf = gs[100 + tid], gg = gs[200 + tid], go = gs[300 + tid];
                float si = 1.f / (1.f + expf(-gi));
                float sf = 1.f / (1.f + expf(-gf));
                float so = 1.f / (1.f + expf(-go));
                float c2 = sf * c[tid] + si * tanhf(gg);
                float h2 = so * tanhf(c2);
                h[tid] = h2; c[tid] = c2;
                g_h[b][t][tid] = h2;
            }
            __syncthreads();
        } else {
            if (tid < 100) g_h[b][t][tid] = h[tid];
        }
    }
}

// ---------------- F: attention readout ----------------
__global__ __launch_bounds__(128) void attn_kernel(const float* __restrict__ b_w,
                                                   float* __restrict__ out) {
    int t = blockIdx.x, b = blockIdx.y, tid = threadIdx.x;
    __shared__ float st[1100], qsm[500], vks[100], lbuf[64], gbuf[64], klb[16], red[2], sql[5];
    __shared__ int sidx[10], ssv[10];
    if (tid < 10) { sidx[tid] = g_idx[b][t][tid]; ssv[tid] = g_sval[b][t][tid]; }
    if (tid >= 16 && tid < 21) sql[tid - 16] = g_ql[b][t][tid - 16];
    __syncthreads();
    for (int i = tid; i < 1100; i += 128) {
        int s = i / 100, d = i % 100;
        int row = (s == 0) ? t : sidx[s - 1];
        st[i] = g_h[b][row][d];
    }
    for (int i = tid; i < 500; i += 128) qsm[i] = (&g_qsc[b][t][0][0])[i];
    for (int d = tid; d < 100; d += 128) vks[d] = g_vk[d];
    __syncthreads();
    float ckb = g_ck + b_w[0];
    if (tid < 55) {
        int q = tid / 11, s = tid % 11;
        bool v = (s == 0) || ssv[s - 1];
        float a = 0.f;
        if (v) {
            const float* qr = qsm + q * 100;
            const float* sr = st + s * 100;
#pragma unroll 4
            for (int d = 0; d < 100; d++) a += qr[d] * sr[d];
        }
        gbuf[tid] = a;
    } else if (tid < 66) {
        int s = tid - 55;
        bool v = (s == 0) || ssv[s - 1];
        float a = -1e30f;
        if (v) {
            a = ckb;
            const float* sr = st + s * 100;
#pragma unroll 4
            for (int d = 0; d < 100; d++) a += sr[d] * vks[d];
        }
        klb[s] = a;
    }
    __syncthreads();
    if (tid < 64) lbuf[tid] = (tid < 55) ? sql[tid / 11] + klb[tid % 11] : -1e30f;
    __syncthreads();
    if (tid < 32) {
        float mx = fmaxf(lbuf[tid], lbuf[tid + 32]);
        for (int o = 16; o > 0; o >>= 1)
            mx = fmaxf(mx, __shfl_xor_sync(0xffffffffu, mx, o));
        if (tid == 0) red[0] = mx;
    }
    __syncthreads();
    if (tid < 64) {
        float e = (tid < 55) ? expf(lbuf[tid] - red[0]) : 0.f;
        lbuf[tid] = e;
        gbuf[tid] = (tid < 55) ? gbuf[tid] * e : 0.f;
    }
    __syncthreads();
    if (tid < 32) {
        float se = lbuf[tid] + lbuf[tid + 32];
        float sp = gbuf[tid] + gbuf[tid + 32];
        for (int o = 16; o > 0; o >>= 1) {
            se += __shfl_xor_sync(0xffffffffu, se, o);
            sp += __shfl_xor_sync(0xffffffffu, sp, o);
        }
        if (tid == 0) out[b * TT + t + 1] = 1.f / (1.f + expf(-sp / se));
    }
}

// ---------------- launch ----------------
extern "C" void kernel_launch(void* const* d_in, const int* in_sizes, int n_in,
                              void* d_out, int out_size) {
    const int* user      = (const int*)d_in[0];
    const int* question  = (const int*)d_in[1];
    const int* response  = (const int*)d_in[2];
    const int* mask      = (const int*)d_in[3];
    const int* q_nb      = (const int*)d_in[4];
    const int* s_nb      = (const int*)d_in[5];
    const int* u_nb      = (const int*)d_in[6];
    const int* q_nb2     = (const int*)d_in[7];
    const int* qs_index  = (const int*)d_in[8];
    const float* emb_q   = (const float*)d_in[9];
    const float* emb_q2  = (const float*)d_in[10];
    const float* emb_s   = (const float*)d_in[11];
    const float* emb_u   = (const float*)d_in[12];
    const float* emb_r   = (const float*)d_in[13];
    const float* w1      = (const float*)d_in[14];
    const float* w2      = (const float*)d_in[15];
    const float* W_ih    = (const float*)d_in[16];
    const float* W_hh    = (const float*)d_in[17];
    const float* b_ih    = (const float*)d_in[18];
    const float* b_hh    = (const float*)d_in[19];
    const float* agg_w   = (const float*)d_in[20];
    const float* agg_b   = (const float*)d_in[21];
    const float* W_al    = (const float*)d_in[22];
    const float* b_al    = (const float*)d_in[23];
    const float* W_query = (const float*)d_in[24];
    const float* b_query = (const float*)d_in[25];
    const float* W_key   = (const float*)d_in[26];
    const float* b_key   = (const float*)d_in[27];
    const float* W_w     = (const float*)d_in[28];
    const float* b_w     = (const float*)d_in[29];
    const float* W_fus   = (const float*)d_in[30];
    const float* b_fus   = (const float*)d_in[31];
    float* out = (float*)d_out;

    const size_t agg_sm  = (5800 + 260) * 4 + 208;    // 24448 B (5800 floats + 260 ints + pad)
    const size_t fus_sm  = 10400 * 4;
    const size_t gat_sm  = 11300 * 4;
    const size_t scan_sm = 40800 * 4;
    cudaFuncSetAttribute(agg_kernel, cudaFuncAttributeMaxDynamicSharedMemorySize, (int)agg_sm);
    cudaFuncSetAttribute(fusion_et_kernel, cudaFuncAttributeMaxDynamicSharedMemorySize, (int)fus_sm);
    cudaFuncSetAttribute(gates_kernel, cudaFuncAttributeMaxDynamicSharedMemorySize, (int)gat_sm);
    cudaFuncSetAttribute(scan_kernel, cudaFuncAttributeMaxDynamicSharedMemorySize, (int)scan_sm);

    // order keeps agg_kernel at launch #4 (profiled slot)
    precompute_qk_kernel<<<2, 128>>>(W_query, b_query, W_key, b_key, W_w);
    transpose_w_kernel<<<2, 256>>>(agg_w);
    precompute_resp_kernel<<<2, 128>>>(emb_r, W_fus, b_fus);
    agg_kernel<<<dim3(TS, TB, 2), 256, agg_sm>>>(user, question, mask, q_nb, s_nb,
                                                 u_nb, q_nb2, emb_q, emb_q2, emb_s,
                                                 emb_u, agg_w, agg_b, W_al, b_al);
    prep_kernel<<<dim3(TS, TB), 128>>>(question, qs_index, emb_q, emb_s);
    fusion_et_kernel<<<dim3(13, TB), 256, fus_sm>>>(response, w1, w2, W_fus);
    gates_kernel<<<dim3(4, 4, TB), 256, gat_sm>>>(W_ih, b_ih, b_hh);
    scan_kernel<<<TB, 256, scan_sm>>>(mask, W_hh, out);
    attn_kernel<<<dim3(TS, TB), 128>>>(b_w, out);
}

// round 8
// speedup vs baseline: 2.3501x; 1.0584x over previous
#include <cuda_runtime.h>

#define TB 32
#define TT 50
#define TS 49
#define DD 100
#define NBR 6
#define SPQ 4
#define RK 10

// ---------------- device scratch (16B-aligned; scalars last) ----------------
__device__ __align__(16) float g_eagg[2][TB][TS][DD];
__device__ __align__(16) float g_gates[TB][TS][4 * DD];
__device__ __align__(16) float g_qsc[TB][TS][5][DD];
__device__ __align__(16) float g_ql[TB][TS][5];
__device__ __align__(16) float g_h[TB][TS][DD];
__device__ __align__(16) int   g_idx[TB][TS][RK];
__device__ __align__(16) int   g_sval[TB][TS][RK];
__device__ __align__(16) float g_vq[DD], g_vk[DD];
__device__ __align__(16) float g_resp[2][DD];
__device__ __align__(16) float g_w1t[10000];   // W1^T : [k*100+d]
__device__ __align__(16) float g_w2t[10000];   // W2^T
__device__ __align__(16) float g_wfT[10000];   // W_fusion(:, 0:100)^T : [k*100+d]
__device__ __align__(16) float g_wihT[40000];  // W_ih^T : [k*400+j]
__device__ float g_cq, g_ck;

#define FMA4(ac, a, w) { ac.x += (a) * (w).x; ac.y += (a) * (w).y; ac.z += (a) * (w).z; ac.w += (a) * (w).w; }

__device__ __forceinline__ float tanha(float x) {
    float y;
    asm("tanh.approx.f32 %0, %1;" : "=f"(y) : "f"(x));
    return y;
}

// ---------------- A1: collapsed qk projections + response fusion half ----------------
__global__ void precompute_kernel(const float* __restrict__ W_query,
                                  const float* __restrict__ b_query,
                                  const float* __restrict__ W_key,
                                  const float* __restrict__ b_key,
                                  const float* __restrict__ W_w,
                                  const float* __restrict__ emb_r,
                                  const float* __restrict__ W_fusion,
                                  const float* __restrict__ b_fusion) {
    int blk = blockIdx.x, tid = threadIdx.x;
    if (blk == 0) {
        for (int k = tid; k < DD; k += 128) {
            float a = 0.f;
            for (int d = 0; d < DD; d++) a += W_query[d * DD + k] * W_w[d];
            g_vq[k] = a;
        }
        if (tid == 0) {
            float c = 0.f;
            for (int d = 0; d < DD; d++) c += b_query[d] * W_w[d];
            g_cq = c;
        }
    } else if (blk == 1) {
        for (int k = tid; k < DD; k += 128) {
            float a = 0.f;
            for (int d = 0; d < DD; d++) a += W_key[d * DD + k] * W_w[DD + d];
            g_vk[k] = a;
        }
        if (tid == 0) {
            float c = 0.f;
            for (int d = 0; d < DD; d++) c += b_key[d] * W_w[DD + d];
            g_ck = c;
        }
    } else {
        int r = blk - 2;
        for (int d = tid; d < DD; d += 128) {
            float a = b_fusion[d];
            for (int k = 0; k < DD; k++)
                a += emb_r[r * DD + k] * W_fusion[d * 2 * DD + DD + k];
            g_resp[r][d] = a;
        }
    }
}

// ---------------- A2: transpose weights into global ----------------
__global__ void transpose_w_kernel(const float* __restrict__ agg_w,
                                   const float* __restrict__ W_fusion,
                                   const float* __restrict__ W_ih) {
    int blk = blockIdx.x, tid = threadIdx.x;
    if (blk == 0) {
        for (int i = tid; i < 10000; i += 256) {
            int d = i / 100, k = i % 100;
            g_w1t[k * 100 + d] = agg_w[10000 + i];
        }
    } else if (blk == 1) {
        for (int i = tid; i < 10000; i += 256) {
            int d = i / 100, k = i % 100;
            g_w2t[k * 100 + d] = agg_w[20000 + i];
        }
    } else if (blk == 2) {
        for (int i = tid; i < 10000; i += 256) {
            int d = i / 100, k = i % 100;
            g_wfT[k * 100 + d] = W_fusion[d * 200 + k];
        }
    } else {  // blk 3..7: W_ih 40000 elems, 8000 each
        int base = (blk - 3) * 8000;
        for (int i = base + tid; i < base + 8000; i += 256) {
            int j = i / 100, k = i - j * 100;
            g_wihT[k * 400 + j] = W_ih[i];
        }
    }
}

// warp-cooperative 100x100 matvec (weights from global, coalesced rows)
__device__ __forceinline__ void mv100(const float* __restrict__ in,
                                      const float* __restrict__ Wg,
                                      const float* __restrict__ bg,
                                      float* out, int tid) {
    int w = tid >> 5, l = tid & 31;
    for (int d = w; d < 100; d += 8) {
        float p = 0.f;
        for (int k = l; k < 100; k += 32) p += in[k] * Wg[d * 100 + k];
        for (int o = 16; o > 0; o >>= 1) p += __shfl_xor_sync(0xffffffffu, p, o);
        if (l == 0) out[d] = tanha(p + bg[d]);
    }
}

// 6x100 matmul, 1x4 tiles (float4 weights), 150 threads
__device__ __forceinline__ void mm6(const float* __restrict__ in,
                                    const float* __restrict__ W1T,
                                    const float* __restrict__ b1g,
                                    float* out, int tid) {
    if (tid < 150) {
        int r = tid / 25, d0 = (tid % 25) * 4;
        float4 ac = make_float4(0, 0, 0, 0);
        const float* xr = in + r * 100;
#pragma unroll 4
        for (int k = 0; k < 100; k++) {
            float4 w = *(const float4*)&W1T[k * 100 + d0];
            FMA4(ac, xr[k], w);
        }
        float* o = out + r * 100 + d0;
        o[0] = tanha(ac.x + b1g[d0]);
        o[1] = tanha(ac.y + b1g[d0 + 1]);
        o[2] = tanha(ac.z + b1g[d0 + 2]);
        o[3] = tanha(ac.w + b1g[d0 + 3]);
    }
}

// ---------------- B: graph aggregation (24 KB smem, 6 CTAs/SM) ----------------
__global__ __launch_bounds__(256, 6) void agg_kernel(
    const int* __restrict__ user, const int* __restrict__ question,
    const int* __restrict__ mask,
    const int* __restrict__ q_nb, const int* __restrict__ s_nb,
    const int* __restrict__ u_nb, const int* __restrict__ q_nb2,
    const float* __restrict__ emb_q, const float* __restrict__ emb_q2,
    const float* __restrict__ emb_s, const float* __restrict__ emb_u,
    const float* __restrict__ agg_w, const float* __restrict__ agg_b,
    const float* __restrict__ W_last, const float* __restrict__ b_last) {
    int t = blockIdx.x, b = blockIdx.y, side = blockIdx.z, tid = threadIdx.x;
    int qt = question[b * TT + t];
    float* outg = &g_eagg[side][b][t][0];
    if (mask[b * TT + t] == 0) {
        const float* src = side ? emb_q2 + (size_t)qt * DD : emb_q + (size_t)qt * DD;
        for (int d = tid; d < DD; d += 256) outg[d] = src[d];
        return;
    }
    extern __shared__ float sm[];
    float* e2s = sm;            // 3600
    float* e1  = e2s + 3600;    // 600
    float* e1b = e1 + 600;      // 600
    float* s6  = e1b + 600;     // 600
    float* e0v = s6 + 600;      // 100
    float* e0b = e0v + 100;     // 100
    float* e0c = e0b + 100;     // 100
    float* s1  = e0c + 100;     // 100  -> 5800 floats
    int* sn1 = (int*)(s1 + 100);  // 8
    int* sn2 = sn1 + 8;           // 36
    int* sn3 = sn2 + 36;          // 216 -> 260 ints

    int n0 = side ? user[b * TT + t] : qt;
    const int* tA = side ? u_nb : q_nb;
    const int* tB = side ? q_nb2 : s_nb;
    const float* eE = side ? emb_u : emb_q;
    const float* eO = side ? emb_q2 : emb_s;
    const float* b0g = agg_b;
    const float* b1g = agg_b + DD;
    const float* b2g = agg_b + 2 * DD;
    const float* W0g = agg_w;

    int g0 = tid / 100;           // 0..2
    int d0i = tid - g0 * 100;

    if (tid < NBR) sn1[tid] = tA[n0 * NBR + tid];
    for (int d = tid; d < 100; d += 256) e0v[d] = eE[(size_t)n0 * DD + d];
    __syncthreads();
    if (tid < 36) sn2[tid] = tB[sn1[tid / 6] * NBR + tid % 6];
    for (int i = tid; i < 600; i += 256)
        e1[i] = eO[(size_t)sn1[i / 100] * DD + i % 100];
    __syncthreads();
    if (tid < 216) sn3[tid] = tA[sn2[tid / 6] * NBR + tid % 6];
    {
        int g = g0, d = d0i;
        for (int i = tid; i < 3600; i += 256) {
            e2s[i] = eE[(size_t)sn2[g] * DD + d];
            d += 56; g += 2;
            if (d >= 100) { d -= 100; ++g; }
        }
    }
    __syncthreads();
    // originals: s6 = groupmean(e2)+e1, s1 = mean(e1)+e0
    for (int i = tid; i < 600; i += 256) {
        int r = i / 100, d = i % 100;
        float s = 0.f;
        for (int r2 = 0; r2 < 6; r2++) s += e2s[(r * 6 + r2) * 100 + d];
        s6[i] = s * (1.f / 6.f) + e1[i];
    }
    if (tid < 100) {
        float s = 0.f;
        for (int r = 0; r < 6; r++) s += e1[r * 100 + tid];
        s1[tid] = s * (1.f / 6.f) + e0v[tid];
    }
    __syncthreads();
    mv100(s1, W0g, b0g, e0b, tid);  // i=0 j=0
    // e2s += hop3 means (gathered), incremental (g,d)
    {
        int g = g0, d = d0i;
        for (int i = tid; i < 3600; i += 256) {
            const int* s3 = sn3 + g * 6;
            float s = eO[(size_t)s3[0] * DD + d] + eO[(size_t)s3[1] * DD + d] +
                      eO[(size_t)s3[2] * DD + d] + eO[(size_t)s3[3] * DD + d] +
                      eO[(size_t)s3[4] * DD + d] + eO[(size_t)s3[5] * DD + d];
            e2s[i] += s * (1.f / 6.f);
            d += 56; g += 2;
            if (d >= 100) { d -= 100; ++g; }
        }
    }
    __syncthreads();
    // i=0 j=2 : 36x100 @ W2^T (global), 4x4 reg tiles, in-place
    float4 ac0, ac1, ac2, ac3;
    int r0 = 0, c0 = 0;
    if (tid < 225) {
        r0 = (tid / 25) * 4; c0 = (tid % 25) * 4;
        ac0 = make_float4(0, 0, 0, 0); ac1 = ac0; ac2 = ac0; ac3 = ac0;
#pragma unroll 2
        for (int k = 0; k < 100; k++) {
            float4 w = *(const float4*)&g_w2t[k * 100 + c0];
            float x0 = e2s[r0 * 100 + k];
            float x1 = e2s[r0 * 100 + 100 + k];
            float x2 = e2s[r0 * 100 + 200 + k];
            float x3 = e2s[r0 * 100 + 300 + k];
            FMA4(ac0, x0, w); FMA4(ac1, x1, w); FMA4(ac2, x2, w); FMA4(ac3, x3, w);
        }
    }
    __syncthreads();
    if (tid < 225) {
        float bb0 = b2g[c0], bb1 = b2g[c0 + 1], bb2 = b2g[c0 + 2], bb3 = b2g[c0 + 3];
        float* o0 = e2s + r0 * 100 + c0;
        o0[0] = tanha(ac0.x + bb0); o0[1] = tanha(ac0.y + bb1); o0[2] = tanha(ac0.z + bb2); o0[3] = tanha(ac0.w + bb3);
        o0[100] = tanha(ac1.x + bb0); o0[101] = tanha(ac1.y + bb1); o0[102] = tanha(ac1.z + bb2); o0[103] = tanha(ac1.w + bb3);
        o0[200] = tanha(ac2.x + bb0); o0[201] = tanha(ac2.y + bb1); o0[202] = tanha(ac2.z + bb2); o0[203] = tanha(ac2.w + bb3);
        o0[300] = tanha(ac3.x + bb0); o0[301] = tanha(ac3.y + bb1); o0[302] = tanha(ac3.z + bb2); o0[303] = tanha(ac3.w + bb3);
    }
    mm6(s6, g_w1t, b1g, e1b, tid);  // i=0 j=1 (reads stable s6)
    __syncthreads();
    for (int i = tid; i < 600; i += 256) {
        int r = i / 100, d = i % 100;
        float s = 0.f;
        for (int r2 = 0; r2 < 6; r2++) s += e2s[(r * 6 + r2) * 100 + d];
        s6[i] = s * (1.f / 6.f) + e1b[i];
    }
    if (tid < 100) {
        float s = 0.f;
        for (int r = 0; r < 6; r++) s += e1b[r * 100 + tid];
        s1[tid] = s * (1.f / 6.f) + e0b[tid];
    }
    __syncthreads();
    mv100(s1, W0g, b0g, e0c, tid);  // i=1 j=0
    mm6(s6, g_w1t, b1g, e1, tid);   // i=1 j=1
    __syncthreads();
    if (tid < 100) {
        float s = 0.f;
        for (int r = 0; r < 6; r++) s += e1[r * 100 + tid];
        s1[tid] = s * (1.f / 6.f) + e0c[tid];
    }
    __syncthreads();
    mv100(s1, W0g, b0g, e0v, tid);  // i=2 j=0
    __syncthreads();
    mv100(e0v, W_last, b_last, outg, tid);  // final
}

// ---------------- C: qs_concat / ql / static top-k ----------------
__global__ __launch_bounds__(128) void prep_kernel(
    const int* __restrict__ question, const int* __restrict__ qs_index,
    const float* __restrict__ emb_q, const float* __restrict__ emb_s) {
    int t = blockIdx.x, b = blockIdx.y, tid = threadIdx.x;
    __shared__ float qsm[500];
    __shared__ float sc[TS];
    int qn = question[b * TT + t + 1];
    for (int i = tid; i < 500; i += 128) {
        int q = i / 100, d = i % 100;
        float v = (q == 0) ? emb_q[(size_t)qn * DD + d]
                           : emb_s[(size_t)qs_index[qn * SPQ + q - 1] * DD + d];
        qsm[i] = v;
        g_qsc[b][t][q][d] = v;
    }
    __syncthreads();
    if (tid < 5) {
        float a = g_cq;
        for (int d = 0; d < 100; d++) a += qsm[tid * 100 + d] * g_vq[d];
        g_ql[b][t][tid] = a;
    }
    for (int i = tid; i < t; i += 128) {
        const float* er = emb_q + (size_t)question[b * TT + i] * DD;
        float a = 0.f;
#pragma unroll 4
        for (int d = 0; d < 100; d++) a += er[d] * qsm[d];
        sc[i] = a;
    }
    __syncthreads();
    if (tid == 0) {
        unsigned long long used = 0ULL;
        for (int s = 0; s < RK; s++) {
            float best = -1e38f; int bi = -1;
            for (int i = 0; i < t; i++)
                if (!((used >> i) & 1ULL) && sc[i] > best) { best = sc[i]; bi = i; }
            if (bi >= 0) { g_idx[b][t][s] = bi; g_sval[b][t][s] = 1; used |= 1ULL << bi; }
            else         { g_idx[b][t][s] = 0;  g_sval[b][t][s] = 0; }
        }
    }
}

// ---------------- D: fused fusion + input gates, grid (13 t-chunks, 32 b) ----------------
__global__ __launch_bounds__(256) void fusion_gates_kernel(
    const int* __restrict__ response, const float* __restrict__ w1p,
    const float* __restrict__ w2p, const float* __restrict__ b_ih,
    const float* __restrict__ b_hh) {
    int tc = blockIdx.x, b = blockIdx.y, tid = threadIdx.x;
    int t0 = tc * 4;
    __shared__ float eh[400], et[400];
    float w1 = *w1p, w2 = *w2p;
    for (int i = tid; i < 400; i += 256) {
        int t = t0 + i / 100, d = i % 100;
        eh[i] = (t < TS) ? w1 * g_eagg[0][b][t][d] + w2 * g_eagg[1][b][t][d] : 0.f;
    }
    __syncthreads();
    if (tid < 100) {
        int tt = tid / 25, d0 = (tid % 25) * 4;
        int t = t0 + tt;
        if (t < TS) {
            float4 ac = make_float4(0, 0, 0, 0);
            const float* x = eh + tt * 100;
#pragma unroll 4
            for (int k = 0; k < 100; k++) {
                float4 w = *(const float4*)&g_wfT[k * 100 + d0];
                FMA4(ac, x[k], w);
            }
            int r = response[b * TT + t];
            et[tt * 100 + d0]     = fmaxf(ac.x + g_resp[r][d0], 0.f);
            et[tt * 100 + d0 + 1] = fmaxf(ac.y + g_resp[r][d0 + 1], 0.f);
            et[tt * 100 + d0 + 2] = fmaxf(ac.z + g_resp[r][d0 + 2], 0.f);
            et[tt * 100 + d0 + 3] = fmaxf(ac.w + g_resp[r][d0 + 3], 0.f);
        }
    }
    __syncthreads();
    for (int u = tid; u < 400; u += 256) {
        int tt = u / 100, j0 = (u % 100) * 4;
        int t = t0 + tt;
        if (t < TS) {
            float4 ac = make_float4(0, 0, 0, 0);
            const float* x = et + tt * 100;
#pragma unroll 4
            for (int k = 0; k < 100; k++) {
                float4 w = *(const float4*)&g_wihT[k * 400 + j0];
                FMA4(ac, x[k], w);
            }
            g_gates[b][t][j0]     = ac.x + b_ih[j0] + b_hh[j0];
            g_gates[b][t][j0 + 1] = ac.y + b_ih[j0 + 1] + b_hh[j0 + 1];
            g_gates[b][t][j0 + 2] = ac.z + b_ih[j0 + 2] + b_hh[j0 + 2];
            g_gates[b][t][j0 + 3] = ac.w + b_ih[j0 + 3] + b_hh[j0 + 3];
        }
    }
}

// ---------------- E: LSTM scan, skip masked steps ----------------
__global__ __launch_bounds__(256) void scan_kernel(
    const int* __restrict__ mask, const float* __restrict__ W_hh,
    float* __restrict__ out) {
    int b = blockIdx.x, tid = threadIdx.x;
    extern __shared__ float sm[];
    float* WT = sm;           // 100*402, WT[d*402+j]
    float* h  = WT + 40200;
    float* c  = h + 100;
    float* gs = c + 100;
    for (int i = tid; i < 40000; i += 256) {
        int j = i / 100, d = i % 100;
        WT[d * 402 + j] = W_hh[i];
    }
    for (int i = tid; i < 100; i += 256) { h[i] = 0.f; c[i] = 0.f; }
    if (tid == 0) out[b * TT] = 0.5f;
    __syncthreads();
    for (int t = 0; t < TS; t++) {
        if (mask[b * TT + t]) {
            if (tid < 200) {
                int j0 = tid * 2;
                float2 gin = *(const float2*)&g_gates[b][t][j0];
                float ax = 0.f, ay = 0.f;
#pragma unroll 4
                for (int d = 0; d < 100; d++) {
                    float hb = h[d];
                    float2 w = *(const float2*)&WT[d * 402 + j0];
                    ax += hb * w.x; ay += hb * w.y;
                }
                gs[j0] = ax + gin.x;
                gs[j0 + 1] = ay + gin.y;
            }
            __syncthreads();
            if (tid < 100) {
                float gi = gs[tid], gf = gs[100 + tid], gg = gs[200 + tid], go = gs[300 + tid];
                float si = 1.f / (1.f + expf(-gi));
                float sf = 1.f / (1.f + expf(-gf));
                float so = 1.f / (1.f + expf(-go));
                float c2 = sf * c[tid] + si * tanhf(gg);
                float h2 = so * tanhf(c2);
                h[tid] = h2; c[tid] = c2;
                g_h[b][t][tid] = h2;
            }
            __syncthreads();
        } else {
            if (tid < 100) g_h[b][t][tid] = h[tid];
        }
    }
}

// ---------------- F: attention readout ----------------
__global__ __launch_bounds__(128) void attn_kernel(const float* __restrict__ b_w,
                                                   float* __restrict__ out) {
    int t = blockIdx.x, b = blockIdx.y, tid = threadIdx.x;
    __shared__ float st[1100], qsm[500], vks[100], lbuf[64], gbuf[64], klb[16], red[2], sql[5];
    __shared__ int sidx[10], ssv[10];
    if (tid < 10) { sidx[tid] = g_idx[b][t][tid]; ssv[tid] = g_sval[b][t][tid]; }
    if (tid >= 16 && tid < 21) sql[tid - 16] = g_ql[b][t][tid - 16];
    __syncthreads();
    for (int i = tid; i < 1100; i += 128) {
        int s = i / 100, d = i % 100;
        int row = (s == 0) ? t : sidx[s - 1];
        st[i] = g_h[b][row][d];
    }
    for (int i = tid; i < 500; i += 128) qsm[i] = (&g_qsc[b][t][0][0])[i];
    for (int d = tid; d < 100; d += 128) vks[d] = g_vk[d];
    __syncthreads();
    float ckb = g_ck + b_w[0];
    if (tid < 55) {
        int q = tid / 11, s = tid % 11;
        bool v = (s == 0) || ssv[s - 1];
        float a = 0.f;
        if (v) {
            const float* qr = qsm + q * 100;
            const float* sr = st + s * 100;
#pragma unroll 4
            for (int d = 0; d < 100; d++) a += qr[d] * sr[d];
        }
        gbuf[tid] = a;
    } else if (tid < 66) {
        int s = tid - 55;
        bool v = (s == 0) || ssv[s - 1];
        float a = -1e30f;
        if (v) {
            a = ckb;
            const float* sr = st + s * 100;
#pragma unroll 4
            for (int d = 0; d < 100; d++) a += sr[d] * vks[d];
        }
        klb[s] = a;
    }
    __syncthreads();
    if (tid < 64) lbuf[tid] = (tid < 55) ? sql[tid / 11] + klb[tid % 11] : -1e30f;
    __syncthreads();
    if (tid < 32) {
        float mx = fmaxf(lbuf[tid], lbuf[tid + 32]);
        for (int o = 16; o > 0; o >>= 1)
            mx = fmaxf(mx, __shfl_xor_sync(0xffffffffu, mx, o));
        if (tid == 0) red[0] = mx;
    }
    __syncthreads();
    if (tid < 64) {
        float e = (tid < 55) ? expf(lbuf[tid] - red[0]) : 0.f;
        lbuf[tid] = e;
        gbuf[tid] = (tid < 55) ? gbuf[tid] * e : 0.f;
    }
    __syncthreads();
    if (tid < 32) {
        float se = lbuf[tid] + lbuf[tid + 32];
        float sp = gbuf[tid] + gbuf[tid + 32];
        for (int o = 16; o > 0; o >>= 1) {
            se += __shfl_xor_sync(0xffffffffu, se, o);
            sp += __shfl_xor_sync(0xffffffffu, sp, o);
        }
        if (tid == 0) out[b * TT + t + 1] = 1.f / (1.f + expf(-sp / se));
    }
}

// ---------------- launch ----------------
extern "C" void kernel_launch(void* const* d_in, const int* in_sizes, int n_in,
                              void* d_out, int out_size) {
    const int* user      = (const int*)d_in[0];
    const int* question  = (const int*)d_in[1];
    const int* response  = (const int*)d_in[2];
    const int* mask      = (const int*)d_in[3];
    const int* q_nb      = (const int*)d_in[4];
    const int* s_nb      = (const int*)d_in[5];
    const int* u_nb      = (const int*)d_in[6];
    const int* q_nb2     = (const int*)d_in[7];
    const int* qs_index  = (const int*)d_in[8];
    const float* emb_q   = (const float*)d_in[9];
    const float* emb_q2  = (const float*)d_in[10];
    const float* emb_s   = (const float*)d_in[11];
    const float* emb_u   = (const float*)d_in[12];
    const float* emb_r   = (const float*)d_in[13];
    const float* w1      = (const float*)d_in[14];
    const float* w2      = (const float*)d_in[15];
    const float* W_ih    = (const float*)d_in[16];
    const float* W_hh    = (const float*)d_in[17];
    const float* b_ih    = (const float*)d_in[18];
    const float* b_hh    = (const float*)d_in[19];
    const float* agg_w   = (const float*)d_in[20];
    const float* agg_b   = (const float*)d_in[21];
    const float* W_al    = (const float*)d_in[22];
    const float* b_al    = (const float*)d_in[23];
    const float* W_query = (const float*)d_in[24];
    const float* b_query = (const float*)d_in[25];
    const float* W_key   = (const float*)d_in[26];
    const float* b_key   = (const float*)d_in[27];
    const float* W_w     = (const float*)d_in[28];
    const float* b_w     = (const float*)d_in[29];
    const float* W_fus   = (const float*)d_in[30];
    const float* b_fus   = (const float*)d_in[31];
    float* out = (float*)d_out;

    const size_t agg_sm  = (5800 + 260) * 4 + 208;    // 24448 B
    const size_t scan_sm = 40800 * 4;
    cudaFuncSetAttribute(agg_kernel, cudaFuncAttributeMaxDynamicSharedMemorySize, (int)agg_sm);
    cudaFuncSetAttribute(scan_kernel, cudaFuncAttributeMaxDynamicSharedMemorySize, (int)scan_sm);

    // agg stays launch #4 (profiled slot)
    precompute_kernel<<<4, 128>>>(W_query, b_query, W_key, b_key, W_w, emb_r, W_fus, b_fus);
    transpose_w_kernel<<<8, 256>>>(agg_w, W_fus, W_ih);
    prep_kernel<<<dim3(TS, TB), 128>>>(question, qs_index, emb_q, emb_s);
    agg_kernel<<<dim3(TS, TB, 2), 256, agg_sm>>>(user, question, mask, q_nb, s_nb,
                                                 u_nb, q_nb2, emb_q, emb_q2, emb_s,
                                                 emb_u, agg_w, agg_b, W_al, b_al);
    fusion_gates_kernel<<<dim3(13, TB), 256>>>(response, w1, w2, b_ih, b_hh);
    scan_kernel<<<TB, 256, scan_sm>>>(mask, W_hh, out);
    attn_kernel<<<dim3(TS, TB), 128>>>(b_w, out);
}

// round 9
// speedup vs baseline: 2.5172x; 1.0711x over previous
#include <cuda_runtime.h>

#define TB 32
#define TT 50
#define TS 49
#define DD 100
#define NBR 6
#define SPQ 4
#define RK 10

// ---------------- device scratch ----------------
__device__ __align__(16) float g_eagg[2][TB][TS][DD];
__device__ __align__(16) float g_gates[TB][TS][4 * DD];
__device__ __align__(16) float g_h[TB][TS][DD];
__device__ __align__(16) float g_vq[DD], g_vk[DD];
__device__ __align__(16) float g_resp[2][DD];
__device__ __align__(16) float g_w1t[10000];   // W1^T : [k*100+d]
__device__ __align__(16) float g_w2t[10000];   // W2^T
__device__ __align__(16) float g_wfT[10000];   // W_fusion(:,0:100)^T : [k*100+d]
__device__ __align__(16) float g_wihT[40000];  // W_ih^T : [k*400+j]
__device__ float g_cq, g_ck;

#define FMA4(ac, a, w) { ac.x += (a) * (w).x; ac.y += (a) * (w).y; ac.z += (a) * (w).z; ac.w += (a) * (w).w; }

__device__ __forceinline__ float tanha(float x) {
    float y;
    asm("tanh.approx.f32 %0, %1;" : "=f"(y) : "f"(x));
    return y;
}

// ---------------- A: precompute + transpose (grid 12) ----------------
__global__ void setup_kernel(const float* __restrict__ W_query,
                             const float* __restrict__ b_query,
                             const float* __restrict__ W_key,
                             const float* __restrict__ b_key,
                             const float* __restrict__ W_w,
                             const float* __restrict__ emb_r,
                             const float* __restrict__ W_fusion,
                             const float* __restrict__ b_fusion,
                             const float* __restrict__ agg_w,
                             const float* __restrict__ W_ih) {
    int blk = blockIdx.x, tid = threadIdx.x;
    if (blk == 0) {
        for (int k = tid; k < DD; k += 256) {
            float a = 0.f;
            for (int d = 0; d < DD; d++) a += W_query[d * DD + k] * W_w[d];
            g_vq[k] = a;
        }
        if (tid == 0) {
            float c = 0.f;
            for (int d = 0; d < DD; d++) c += b_query[d] * W_w[d];
            g_cq = c;
        }
    } else if (blk == 1) {
        for (int k = tid; k < DD; k += 256) {
            float a = 0.f;
            for (int d = 0; d < DD; d++) a += W_key[d * DD + k] * W_w[DD + d];
            g_vk[k] = a;
        }
        if (tid == 0) {
            float c = 0.f;
            for (int d = 0; d < DD; d++) c += b_key[d] * W_w[DD + d];
            g_ck = c;
        }
    } else if (blk <= 3) {
        int r = blk - 2;
        for (int d = tid; d < DD; d += 256) {
            float a = b_fusion[d];
            for (int k = 0; k < DD; k++)
                a += emb_r[r * DD + k] * W_fusion[d * 2 * DD + DD + k];
            g_resp[r][d] = a;
        }
    } else if (blk == 4) {
        for (int i = tid; i < 10000; i += 256) {
            int d = i / 100, k = i % 100;
            g_w1t[k * 100 + d] = agg_w[10000 + i];
        }
    } else if (blk == 5) {
        for (int i = tid; i < 10000; i += 256) {
            int d = i / 100, k = i % 100;
            g_w2t[k * 100 + d] = agg_w[20000 + i];
        }
    } else if (blk == 6) {
        for (int i = tid; i < 10000; i += 256) {
            int d = i / 100, k = i % 100;
            g_wfT[k * 100 + d] = W_fusion[d * 200 + k];
        }
    } else {  // blk 7..11: W_ih 40000 elems, 8000 each
        int base = (blk - 7) * 8000;
        for (int i = base + tid; i < base + 8000; i += 256) {
            int j = i / 100, k = i - j * 100;
            g_wihT[k * 400 + j] = W_ih[i];
        }
    }
}

// warp-cooperative 100x100 matvec (weights from global, coalesced rows)
__device__ __forceinline__ void mv100(const float* __restrict__ in,
                                      const float* __restrict__ Wg,
                                      const float* __restrict__ bg,
                                      float* out, int tid) {
    int w = tid >> 5, l = tid & 31;
    for (int d = w; d < 100; d += 8) {
        float p = 0.f;
        for (int k = l; k < 100; k += 32) p += in[k] * Wg[d * 100 + k];
        for (int o = 16; o > 0; o >>= 1) p += __shfl_xor_sync(0xffffffffu, p, o);
        if (l == 0) out[d] = tanha(p + bg[d]);
    }
}

// 6x100 matmul, 2x2 reg tiles (float2 weights), 150 threads
__device__ __forceinline__ void mm6(const float* __restrict__ in,
                                    const float* __restrict__ W1T,
                                    const float* __restrict__ b1g,
                                    float* out, int tid) {
    if (tid < 150) {
        int r0 = (tid / 50) * 2, d0 = (tid % 50) * 2;
        float a00 = 0.f, a01 = 0.f, a10 = 0.f, a11 = 0.f;
#pragma unroll 4
        for (int k = 0; k < 100; k++) {
            float2 w = *(const float2*)&W1T[k * 100 + d0];
            float x0 = in[r0 * 100 + k], x1 = in[r0 * 100 + 100 + k];
            a00 += x0 * w.x; a01 += x0 * w.y;
            a10 += x1 * w.x; a11 += x1 * w.y;
        }
        float b0 = b1g[d0], b1 = b1g[d0 + 1];
        out[r0 * 100 + d0] = tanha(a00 + b0);
        out[r0 * 100 + d0 + 1] = tanha(a01 + b1);
        out[r0 * 100 + 100 + d0] = tanha(a10 + b0);
        out[r0 * 100 + 100 + d0 + 1] = tanha(a11 + b1);
    }
}

// ---------------- B: graph aggregation ----------------
__global__ __launch_bounds__(256, 6) void agg_kernel(
    const int* __restrict__ user, const int* __restrict__ question,
    const int* __restrict__ mask,
    const int* __restrict__ q_nb, const int* __restrict__ s_nb,
    const int* __restrict__ u_nb, const int* __restrict__ q_nb2,
    const float* __restrict__ emb_q, const float* __restrict__ emb_q2,
    const float* __restrict__ emb_s, const float* __restrict__ emb_u,
    const float* __restrict__ agg_w, const float* __restrict__ agg_b,
    const float* __restrict__ W_last, const float* __restrict__ b_last) {
    int t = blockIdx.x, b = blockIdx.y, side = blockIdx.z, tid = threadIdx.x;
    int qt = question[b * TT + t];
    float* outg = &g_eagg[side][b][t][0];
    if (mask[b * TT + t] == 0) {
        const float* src = side ? emb_q2 + (size_t)qt * DD : emb_q + (size_t)qt * DD;
        for (int d = tid; d < DD; d += 256) outg[d] = src[d];
        return;
    }
    extern __shared__ float sm[];
    float* e2s = sm;            // 3600
    float* e1  = e2s + 3600;    // 600
    float* e1b = e1 + 600;      // 600
    float* s6  = e1b + 600;     // 600
    float* e0v = s6 + 600;      // 100
    float* e0b = e0v + 100;     // 100
    float* e0c = e0b + 100;     // 100
    float* s1  = e0c + 100;     // 100  -> 5800 floats
    int* sn1 = (int*)(s1 + 100);  // 8
    int* sn2 = sn1 + 8;           // 36
    int* sn3 = sn2 + 36;          // 216 -> 260 ints

    int n0 = side ? user[b * TT + t] : qt;
    const int* tA = side ? u_nb : q_nb;
    const int* tB = side ? q_nb2 : s_nb;
    const float* eE = side ? emb_u : emb_q;
    const float* eO = side ? emb_q2 : emb_s;
    const float* b0g = agg_b;
    const float* b1g = agg_b + DD;
    const float* b2g = agg_b + 2 * DD;
    const float* W0g = agg_w;

    int g0 = tid / 100;
    int d0i = tid - g0 * 100;

    if (tid < NBR) sn1[tid] = tA[n0 * NBR + tid];
    for (int d = tid; d < 100; d += 256) e0v[d] = eE[(size_t)n0 * DD + d];
    __syncthreads();
    if (tid < 36) sn2[tid] = tB[sn1[tid / 6] * NBR + tid % 6];
    for (int i = tid; i < 600; i += 256)
        e1[i] = eO[(size_t)sn1[i / 100] * DD + i % 100];
    __syncthreads();
    if (tid < 216) sn3[tid] = tA[sn2[tid / 6] * NBR + tid % 6];
    {
        int g = g0, d = d0i;
        for (int i = tid; i < 3600; i += 256) {
            e2s[i] = eE[(size_t)sn2[g] * DD + d];
            d += 56; g += 2;
            if (d >= 100) { d -= 100; ++g; }
        }
    }
    __syncthreads();
    for (int i = tid; i < 600; i += 256) {
        int r = i / 100, d = i % 100;
        float s = 0.f;
        for (int r2 = 0; r2 < 6; r2++) s += e2s[(r * 6 + r2) * 100 + d];
        s6[i] = s * (1.f / 6.f) + e1[i];
    }
    if (tid < 100) {
        float s = 0.f;
        for (int r = 0; r < 6; r++) s += e1[r * 100 + tid];
        s1[tid] = s * (1.f / 6.f) + e0v[tid];
    }
    __syncthreads();
    mv100(s1, W0g, b0g, e0b, tid);  // i=0 j=0
    {
        int g = g0, d = d0i;
        for (int i = tid; i < 3600; i += 256) {
            const int* s3 = sn3 + g * 6;
            float s = eO[(size_t)s3[0] * DD + d] + eO[(size_t)s3[1] * DD + d] +
                      eO[(size_t)s3[2] * DD + d] + eO[(size_t)s3[3] * DD + d] +
                      eO[(size_t)s3[4] * DD + d] + eO[(size_t)s3[5] * DD + d];
            e2s[i] += s * (1.f / 6.f);
            d += 56; g += 2;
            if (d >= 100) { d -= 100; ++g; }
        }
    }
    __syncthreads();
    // i=0 j=2 : 36x100 @ W2^T, 4x4 reg tiles, in-place
    float4 ac0, ac1, ac2, ac3;
    int r0 = 0, c0 = 0;
    if (tid < 225) {
        r0 = (tid / 25) * 4; c0 = (tid % 25) * 4;
        ac0 = make_float4(0, 0, 0, 0); ac1 = ac0; ac2 = ac0; ac3 = ac0;
#pragma unroll 2
        for (int k = 0; k < 100; k++) {
            float4 w = *(const float4*)&g_w2t[k * 100 + c0];
            float x0 = e2s[r0 * 100 + k];
            float x1 = e2s[r0 * 100 + 100 + k];
            float x2 = e2s[r0 * 100 + 200 + k];
            float x3 = e2s[r0 * 100 + 300 + k];
            FMA4(ac0, x0, w); FMA4(ac1, x1, w); FMA4(ac2, x2, w); FMA4(ac3, x3, w);
        }
    }
    __syncthreads();
    if (tid < 225) {
        float bb0 = b2g[c0], bb1 = b2g[c0 + 1], bb2 = b2g[c0 + 2], bb3 = b2g[c0 + 3];
        float* o0 = e2s + r0 * 100 + c0;
        o0[0] = tanha(ac0.x + bb0); o0[1] = tanha(ac0.y + bb1); o0[2] = tanha(ac0.z + bb2); o0[3] = tanha(ac0.w + bb3);
        o0[100] = tanha(ac1.x + bb0); o0[101] = tanha(ac1.y + bb1); o0[102] = tanha(ac1.z + bb2); o0[103] = tanha(ac1.w + bb3);
        o0[200] = tanha(ac2.x + bb0); o0[201] = tanha(ac2.y + bb1); o0[202] = tanha(ac2.z + bb2); o0[203] = tanha(ac2.w + bb3);
        o0[300] = tanha(ac3.x + bb0); o0[301] = tanha(ac3.y + bb1); o0[302] = tanha(ac3.z + bb2); o0[303] = tanha(ac3.w + bb3);
    }
    mm6(s6, g_w1t, b1g, e1b, tid);  // i=0 j=1
    __syncthreads();
    for (int i = tid; i < 600; i += 256) {
        int r = i / 100, d = i % 100;
        float s = 0.f;
        for (int r2 = 0; r2 < 6; r2++) s += e2s[(r * 6 + r2) * 100 + d];
        s6[i] = s * (1.f / 6.f) + e1b[i];
    }
    if (tid < 100) {
        float s = 0.f;
        for (int r = 0; r < 6; r++) s += e1b[r * 100 + tid];
        s1[tid] = s * (1.f / 6.f) + e0b[tid];
    }
    __syncthreads();
    mv100(s1, W0g, b0g, e0c, tid);  // i=1 j=0
    mm6(s6, g_w1t, b1g, e1, tid);   // i=1 j=1
    __syncthreads();
    if (tid < 100) {
        float s = 0.f;
        for (int r = 0; r < 6; r++) s += e1[r * 100 + tid];
        s1[tid] = s * (1.f / 6.f) + e0c[tid];
    }
    __syncthreads();
    mv100(s1, W0g, b0g, e0v, tid);  // i=2 j=0
    __syncthreads();
    mv100(e0v, W_last, b_last, outg, tid);  // final
}

// ---------------- C: fused fusion + input gates ----------------
__global__ __launch_bounds__(256) void fusion_gates_kernel(
    const int* __restrict__ response, const float* __restrict__ w1p,
    const float* __restrict__ w2p, const float* __restrict__ b_ih,
    const float* __restrict__ b_hh) {
    int tc = blockIdx.x, b = blockIdx.y, tid = threadIdx.x;
    int t0 = tc * 4;
    __shared__ float eh[400], et[400];
    float w1 = *w1p, w2 = *w2p;
    for (int i = tid; i < 400; i += 256) {
        int t = t0 + i / 100, d = i % 100;
        eh[i] = (t < TS) ? w1 * g_eagg[0][b][t][d] + w2 * g_eagg[1][b][t][d] : 0.f;
    }
    __syncthreads();
    if (tid < 100) {
        int tt = tid / 25, d0 = (tid % 25) * 4;
        int t = t0 + tt;
        if (t < TS) {
            float4 ac = make_float4(0, 0, 0, 0);
            const float* x = eh + tt * 100;
#pragma unroll 4
            for (int k = 0; k < 100; k++) {
                float4 w = *(const float4*)&g_wfT[k * 100 + d0];
                FMA4(ac, x[k], w);
            }
            int r = response[b * TT + t];
            et[tt * 100 + d0]     = fmaxf(ac.x + g_resp[r][d0], 0.f);
            et[tt * 100 + d0 + 1] = fmaxf(ac.y + g_resp[r][d0 + 1], 0.f);
            et[tt * 100 + d0 + 2] = fmaxf(ac.z + g_resp[r][d0 + 2], 0.f);
            et[tt * 100 + d0 + 3] = fmaxf(ac.w + g_resp[r][d0 + 3], 0.f);
        }
    }
    __syncthreads();
    for (int u = tid; u < 400; u += 256) {
        int tt = u / 100, j0 = (u % 100) * 4;
        int t = t0 + tt;
        if (t < TS) {
            float4 ac = make_float4(0, 0, 0, 0);
            const float* x = et + tt * 100;
#pragma unroll 4
            for (int k = 0; k < 100; k++) {
                float4 w = *(const float4*)&g_wihT[k * 400 + j0];
                FMA4(ac, x[k], w);
            }
            g_gates[b][t][j0]     = ac.x + b_ih[j0] + b_hh[j0];
            g_gates[b][t][j0 + 1] = ac.y + b_ih[j0 + 1] + b_hh[j0 + 1];
            g_gates[b][t][j0 + 2] = ac.z + b_ih[j0 + 2] + b_hh[j0 + 2];
            g_gates[b][t][j0 + 3] = ac.w + b_ih[j0 + 3] + b_hh[j0 + 3];
        }
    }
}

// ---------------- D: LSTM scan ----------------
__global__ __launch_bounds__(256) void scan_kernel(
    const int* __restrict__ mask, const float* __restrict__ W_hh,
    float* __restrict__ out) {
    int b = blockIdx.x, tid = threadIdx.x;
    extern __shared__ float sm[];
    float* WT = sm;           // 100*402, WT[d*402+j]
    float* h  = WT + 40200;
    float* c  = h + 100;
    float* gs = c + 100;
    for (int i = tid; i < 40000; i += 256) {
        int j = i / 100, d = i % 100;
        WT[d * 402 + j] = W_hh[i];
    }
    for (int i = tid; i < 100; i += 256) { h[i] = 0.f; c[i] = 0.f; }
    if (tid == 0) out[b * TT] = 0.5f;
    __syncthreads();
    for (int t = 0; t < TS; t++) {
        if (mask[b * TT + t]) {
            if (tid < 200) {
                int j0 = tid * 2;
                float2 gin = *(const float2*)&g_gates[b][t][j0];
                float ax = 0.f, ay = 0.f;
#pragma unroll 4
                for (int d = 0; d < 100; d++) {
                    float hb = h[d];
                    float2 w = *(const float2*)&WT[d * 402 + j0];
                    ax += hb * w.x; ay += hb * w.y;
                }
                gs[j0] = ax + gin.x;
                gs[j0 + 1] = ay + gin.y;
            }
            __syncthreads();
            if (tid < 100) {
                float gi = gs[tid], gf = gs[100 + tid], gg = gs[200 + tid], go = gs[300 + tid];
                float si = 1.f / (1.f + expf(-gi));
                float sf = 1.f / (1.f + expf(-gf));
                float so = 1.f / (1.f + expf(-go));
                float c2 = sf * c[tid] + si * tanhf(gg);
                float h2 = so * tanhf(c2);
                h[tid] = h2; c[tid] = c2;
                g_h[b][t][tid] = h2;
            }
            __syncthreads();
        } else {
            if (tid < 100) g_h[b][t][tid] = h[tid];
        }
    }
}

// ---------------- E: prep + attention fused, grid (TS, TB) ----------------
__global__ __launch_bounds__(128) void attn_kernel(
    const int* __restrict__ question, const int* __restrict__ qs_index,
    const float* __restrict__ emb_q, const float* __restrict__ emb_s,
    const float* __restrict__ b_w, float* __restrict__ out) {
    int t = blockIdx.x, b = blockIdx.y, tid = threadIdx.x;
    __shared__ float st[1100], qsm[500], vks[100], sc[52], lbuf[64], gbuf[64],
                     klb[16], red[2], sql[5];
    __shared__ int sidx[10], ssv[10];
    int qn = question[b * TT + t + 1];
    for (int i = tid; i < 500; i += 128) {
        int q = i / 100, d = i % 100;
        qsm[i] = (q == 0) ? emb_q[(size_t)qn * DD + d]
                          : emb_s[(size_t)qs_index[qn * SPQ + q - 1] * DD + d];
    }
    for (int d = tid; d < 100; d += 128) vks[d] = g_vk[d];
    __syncthreads();
    if (tid < 5) {
        float a = g_cq;
        for (int d = 0; d < 100; d++) a += qsm[tid * 100 + d] * g_vq[d];
        sql[tid] = a;
    }
    for (int i = tid; i < t; i += 128) {
        const float* er = emb_q + (size_t)question[b * TT + i] * DD;
        float a = 0.f;
#pragma unroll 4
        for (int d = 0; d < 100; d++) a += er[d] * qsm[d];
        sc[i] = a;
    }
    __syncthreads();
    if (tid == 0) {  // exact stable top-k over i < t
        unsigned long long used = 0ULL;
        for (int s = 0; s < RK; s++) {
            float best = -1e38f; int bi = -1;
            for (int i = 0; i < t; i++)
                if (!((used >> i) & 1ULL) && sc[i] > best) { best = sc[i]; bi = i; }
            if (bi >= 0) { sidx[s] = bi; ssv[s] = 1; used |= 1ULL << bi; }
            else         { sidx[s] = 0;  ssv[s] = 0; }
        }
    }
    __syncthreads();
    for (int i = tid; i < 1100; i += 128) {
        int s = i / 100, d = i % 100;
        int row = (s == 0) ? t : sidx[s - 1];
        st[i] = g_h[b][row][d];
    }
    __syncthreads();
    float ckb = g_ck + b_w[0];
    if (tid < 55) {
        int q = tid / 11, s = tid % 11;
        bool v = (s == 0) || ssv[s - 1];
        float a = 0.f;
        if (v) {
            const float* qr = qsm + q * 100;
            const float* sr = st + s * 100;
#pragma unroll 4
            for (int d = 0; d < 100; d++) a += qr[d] * sr[d];
        }
        gbuf[tid] = a;
    } else if (tid < 66) {
        int s = tid - 55;
        bool v = (s == 0) || ssv[s - 1];
        float a = -1e30f;
        if (v) {
            a = ckb;
            const float* sr = st + s * 100;
#pragma unroll 4
            for (int d = 0; d < 100; d++) a += sr[d] * vks[d];
        }
        klb[s] = a;
    }
    __syncthreads();
    if (tid < 64) lbuf[tid] = (tid < 55) ? sql[tid / 11] + klb[tid % 11] : -1e30f;
    __syncthreads();
    if (tid < 32) {
        float mx = fmaxf(lbuf[tid], lbuf[tid + 32]);
        for (int o = 16; o > 0; o >>= 1)
            mx = fmaxf(mx, __shfl_xor_sync(0xffffffffu, mx, o));
        if (tid == 0) red[0] = mx;
    }
    __syncthreads();
    if (tid < 64) {
        float e = (tid < 55) ? expf(lbuf[tid] - red[0]) : 0.f;
        lbuf[tid] = e;
        gbuf[tid] = (tid < 55) ? gbuf[tid] * e : 0.f;
    }
    __syncthreads();
    if (tid < 32) {
        float se = lbuf[tid] + lbuf[tid + 32];
        float sp = gbuf[tid] + gbuf[tid + 32];
        for (int o = 16; o > 0; o >>= 1) {
            se += __shfl_xor_sync(0xffffffffu, se, o);
            sp += __shfl_xor_sync(0xffffffffu, sp, o);
        }
        if (tid == 0) out[b * TT + t + 1] = 1.f / (1.f + expf(-sp / se));
    }
}

// ---------------- launch ----------------
extern "C" void kernel_launch(void* const* d_in, const int* in_sizes, int n_in,
                              void* d_out, int out_size) {
    const int* user      = (const int*)d_in[0];
    const int* question  = (const int*)d_in[1];
    const int* response  = (const int*)d_in[2];
    const int* mask      = (const int*)d_in[3];
    const int* q_nb      = (const int*)d_in[4];
    const int* s_nb      = (const int*)d_in[5];
    const int* u_nb      = (const int*)d_in[6];
    const int* q_nb2     = (const int*)d_in[7];
    const int* qs_index  = (const int*)d_in[8];
    const float* emb_q   = (const float*)d_in[9];
    const float* emb_q2  = (const float*)d_in[10];
    const float* emb_s   = (const float*)d_in[11];
    const float* emb_u   = (const float*)d_in[12];
    const float* emb_r   = (const float*)d_in[13];
    const float* w1      = (const float*)d_in[14];
    const float* w2      = (const float*)d_in[15];
    const float* W_ih    = (const float*)d_in[16];
    const float* W_hh    = (const float*)d_in[17];
    const float* b_ih    = (const float*)d_in[18];
    const float* b_hh    = (const float*)d_in[19];
    const float* agg_w   = (const float*)d_in[20];
    const float* agg_b   = (const float*)d_in[21];
    const float* W_al    = (const float*)d_in[22];
    const float* b_al    = (const float*)d_in[23];
    const float* W_query = (const float*)d_in[24];
    const float* b_query = (const float*)d_in[25];
    const float* W_key   = (const float*)d_in[26];
    const float* b_key   = (const float*)d_in[27];
    const float* W_w     = (const float*)d_in[28];
    const float* b_w     = (const float*)d_in[29];
    const float* W_fus   = (const float*)d_in[30];
    const float* b_fus   = (const float*)d_in[31];
    float* out = (float*)d_out;

    const size_t agg_sm  = (5800 + 260) * 4 + 208;    // 24448 B
    const size_t scan_sm = 40800 * 4;
    cudaFuncSetAttribute(agg_kernel, cudaFuncAttributeMaxDynamicSharedMemorySize, (int)agg_sm);
    cudaFuncSetAttribute(scan_kernel, cudaFuncAttributeMaxDynamicSharedMemorySize, (int)scan_sm);

    setup_kernel<<<12, 256>>>(W_query, b_query, W_key, b_key, W_w, emb_r, W_fus,
                              b_fus, agg_w, W_ih);
    agg_kernel<<<dim3(TS, TB, 2), 256, agg_sm>>>(user, question, mask, q_nb, s_nb,
                                                 u_nb, q_nb2, emb_q, emb_q2, emb_s,
                                                 emb_u, agg_w, agg_b, W_al, b_al);
    fusion_gates_kernel<<<dim3(13, TB), 256>>>(response, w1, w2, b_ih, b_hh);
    scan_kernel<<<TB, 256, scan_sm>>>(mask, W_hh, out);   // profiled slot #4
    attn_kernel<<<dim3(TS, TB), 128>>>(question, qs_index, emb_q, emb_s, b_w, out);
}